// round 1
// baseline (speedup 1.0000x reference)
#include <cuda_runtime.h>
#include <cuda_bf16.h>
#include <math.h>

#define NB 32
#define NG 60
#define NC 80
#define NA 8400
#define A0 6400
#define A1 8000
#define TK 10

// ---------------- device scratch (static, allowed) ----------------
__device__ float4 d_box[NB * NA];           // decoded boxes (cx,cy,w,h)
__device__ float  d_obj[NB * NA];           // objectness logits
__device__ float  d_sps[NB * NA];           // sum_c softplus(cls_lo) (for loss)
__device__ float  d_b0s[NB * NA];           // sum_c -log(1-p)        (for cost)
__device__ float  d_dco[(size_t)NB * NC * NA]; // per-class (bce1-bce0), layout [b][c][a]
__device__ float  d_iou[(size_t)NB * NG * NA];
__device__ float  d_cst[(size_t)NB * NG * NA];
__device__ unsigned char d_fg[NB * NA];
__device__ int    d_pos[NB * NG * TK];
__device__ int    d_dynk[NB * NG];
__device__ int    d_cnt[NB * NA];
__device__ int    d_lastg[NB * NA];
__device__ int    d_matched[NB * NA];
__device__ float  d_prediou[NB * NA];
__device__ double d_acc[4]; // iou, obj, cls, nfg

__device__ __forceinline__ void ainfo(int a, float& st, float& cxa, float& cya) {
    int hw, W;
    if (a < A0)      { st = 8.f;  hw = a;      W = 80; }
    else if (a < A1) { st = 16.f; hw = a - A0; W = 40; }
    else             { st = 32.f; hw = a - A1; W = 20; }
    int x = hw % W, y = hw / W;
    cxa = (x + 0.5f) * st;
    cya = (y + 0.5f) * st;
}

// ---------------- kernels ----------------
__global__ void k_zero() {
    int i = blockIdx.x * blockDim.x + threadIdx.x;
    if (i < NB * NA) d_cnt[i] = 0;
    if (i < 4) d_acc[i] = 0.0;
}

__global__ void k_decode(const float* __restrict__ f8,
                         const float* __restrict__ f16,
                         const float* __restrict__ f32_) {
    int i = blockIdx.x * blockDim.x + threadIdx.x;
    if (i >= NB * NA) return;
    int b = i / NA, a = i % NA;
    const float* f; int hw, HW, W; float st;
    if (a < A0)      { f = f8;   hw = a;      HW = 6400; W = 80; st = 8.f;  }
    else if (a < A1) { f = f16;  hw = a - A0; HW = 1600; W = 40; st = 16.f; }
    else             { f = f32_; hw = a - A1; HW = 400;  W = 20; st = 32.f; }
    float gx = (float)(hw % W), gy = (float)(hw / W);
    const float* base = f + (size_t)b * (5 + NC) * HW + hw;
    float tx = base[0 * HW], ty = base[(size_t)1 * HW];
    float tw = base[(size_t)2 * HW], th = base[(size_t)3 * HW];
    float to = base[(size_t)4 * HW];
    float4 bx;
    bx.x = (tx + gx) * st; bx.y = (ty + gy) * st;
    bx.z = expf(tw) * st;  bx.w = expf(th) * st;
    d_box[i] = bx;
    d_obj[i] = to;
    float so = 1.f / (1.f + expf(-to));
    float sps = 0.f, b0s = 0.f;
    for (int c = 0; c < NC; c++) {
        float x = base[(size_t)(5 + c) * HW];
        float sc = 1.f / (1.f + expf(-x));
        float p = sqrtf(sc * so);
        p = fminf(fmaxf(p, 1e-7f), 1.f - 1e-7f);
        float bce1 = -logf(p);
        float bce0 = -logf(1.f - p);
        b0s += bce0;
        d_dco[((size_t)b * NC + c) * NA + a] = bce1 - bce0;
        sps += fmaxf(x, 0.f) + log1pf(expf(-fabsf(x)));
    }
    d_sps[i] = sps;
    d_b0s[i] = b0s;
}

__global__ void k_fg(const float* __restrict__ gtb, const int* __restrict__ ngts) {
    int i = blockIdx.x * blockDim.x + threadIdx.x;
    if (i >= NB * NA) return;
    int b = i / NA, a = i % NA;
    float st, cxa, cya;
    ainfo(a, st, cxa, cya);
    int n = ngts[b];
    bool fg = false;
    const float R = 2.5f;
    for (int g = 0; g < n; g++) {
        const float* gb = gtb + ((size_t)b * NG + g) * 4;
        float gx = gb[0], gy = gb[1], gw = gb[2], gh = gb[3];
        bool in_box = (cxa > gx - 0.5f * gw) && (cxa < gx + 0.5f * gw) &&
                      (cya > gy - 0.5f * gh) && (cya < gy + 0.5f * gh);
        bool in_ctr = (cxa > gx - R * st) && (cxa < gx + R * st) &&
                      (cya > gy - R * st) && (cya < gy + R * st);
        fg = fg || in_box || in_ctr;
    }
    d_fg[i] = fg ? 1 : 0;
}

__global__ void k_cost(const float* __restrict__ gtb, const int* __restrict__ gtc,
                       const int* __restrict__ ngts) {
    int a = blockIdx.x * blockDim.x + threadIdx.x;
    if (a >= NA) return;
    int g = blockIdx.y, b = blockIdx.z;
    const float* gb = gtb + ((size_t)b * NG + g) * 4;
    float gx = gb[0], gy = gb[1], gw = gb[2], gh = gb[3];
    bool valid = g < ngts[b];
    float4 pb = d_box[b * NA + a];
    // pairwise IoU
    float tlx = fmaxf(gx - gw * 0.5f, pb.x - pb.z * 0.5f);
    float tly = fmaxf(gy - gh * 0.5f, pb.y - pb.w * 0.5f);
    float brx = fminf(gx + gw * 0.5f, pb.x + pb.z * 0.5f);
    float bry = fminf(gy + gh * 0.5f, pb.y + pb.w * 0.5f);
    bool en = (tlx < brx) && (tly < bry);
    float inter = en ? (brx - tlx) * (bry - tly) : 0.f;
    float iou = inter / (gw * gh + pb.z * pb.w - inter + 1e-16f);
    size_t idx = ((size_t)(b * NG + g)) * NA + a;
    d_iou[idx] = iou;
    // geometry
    float st, cxa, cya;
    ainfo(a, st, cxa, cya);
    const float R = 2.5f;
    bool in_box = (cxa > gx - 0.5f * gw) && (cxa < gx + 0.5f * gw) &&
                  (cya > gy - 0.5f * gh) && (cya < gy + 0.5f * gh);
    bool in_ctr = (cxa > gx - R * st) && (cxa < gx + R * st) &&
                  (cya > gy - R * st) && (cya < gy + R * st);
    bool in_both = in_box && in_ctr;
    int gc = gtc[b * NG + g];
    float cost = d_b0s[b * NA + a] + d_dco[((size_t)b * NC + gc) * NA + a];
    cost += 3.0f * (-logf(iou + 1e-8f));
    cost += 100000.0f * (1.0f - (in_both ? 1.f : 0.f));
    cost += d_fg[b * NA + a] ? 0.f : 1000000000.0f;
    cost += valid ? 0.f : 1000000000.0f;
    d_cst[idx] = cost;
}

__global__ void k_topk(const int* __restrict__ ngts) {
    __shared__ float sv[NA];
    __shared__ float rv[256];
    __shared__ int   ri[256];
    __shared__ int   s_bi;
    int g = blockIdx.x, b = blockIdx.y, tid = threadIdx.x;
    if (g >= ngts[b]) return;
    size_t row = ((size_t)(b * NG + g)) * NA;
    // --- dyn_k: top-10 of iou*fg (values only, descending sum) ---
    for (int j = tid; j < NA; j += 256)
        sv[j] = d_fg[b * NA + j] ? d_iou[row + j] : 0.f;
    __syncthreads();
    float ksum = 0.f;
    for (int it = 0; it < TK; it++) {
        float bv = -1.f; int bi = NA;
        for (int j = tid; j < NA; j += 256) {
            float v = sv[j];
            if (v > bv || (v == bv && j < bi)) { bv = v; bi = j; }
        }
        rv[tid] = bv; ri[tid] = bi; __syncthreads();
        for (int s = 128; s > 0; s >>= 1) {
            if (tid < s) {
                float ov = rv[tid + s]; int oi = ri[tid + s];
                if (ov > rv[tid] || (ov == rv[tid] && oi < ri[tid])) { rv[tid] = ov; ri[tid] = oi; }
            }
            __syncthreads();
        }
        if (tid == 0) { ksum += rv[0]; s_bi = ri[0]; }
        __syncthreads();
        if (tid == 0) sv[s_bi] = -1.f;
        __syncthreads();
    }
    if (tid == 0) {
        int dk = (int)ksum;
        if (dk < 1) dk = 1;
        d_dynk[b * NG + g] = dk;
    }
    // --- pos: 10 smallest costs, ties -> smallest index ---
    for (int j = tid; j < NA; j += 256) sv[j] = d_cst[row + j];
    __syncthreads();
    for (int it = 0; it < TK; it++) {
        float bv = 3.4e38f; int bi = NA;
        for (int j = tid; j < NA; j += 256) {
            float v = sv[j];
            if (v < bv || (v == bv && j < bi)) { bv = v; bi = j; }
        }
        rv[tid] = bv; ri[tid] = bi; __syncthreads();
        for (int s = 128; s > 0; s >>= 1) {
            if (tid < s) {
                float ov = rv[tid + s]; int oi = ri[tid + s];
                if (ov < rv[tid] || (ov == rv[tid] && oi < ri[tid])) { rv[tid] = ov; ri[tid] = oi; }
            }
            __syncthreads();
        }
        if (tid == 0) { d_pos[(b * NG + g) * TK + it] = ri[0]; s_bi = ri[0]; }
        __syncthreads();
        if (tid == 0) sv[s_bi] = 3.4e38f;
        __syncthreads();
    }
}

__global__ void k_scatter(const int* __restrict__ ngts) {
    int i = blockIdx.x * blockDim.x + threadIdx.x;
    if (i >= NB * NG) return;
    int b = i / NG, g = i % NG;
    if (g >= ngts[b]) return;
    int dk = d_dynk[i];
    for (int k = 0; k < dk; k++) {
        int a = d_pos[i * TK + k];
        atomicAdd(&d_cnt[b * NA + a], 1);
        d_lastg[b * NA + a] = g;
    }
}

__global__ void k_resolve() {
    int i = blockIdx.x * blockDim.x + threadIdx.x;
    if (i >= NB * NA) return;
    int b = i / NA, a = i % NA;
    int c = d_cnt[i];
    if (c == 0) { d_matched[i] = -1; d_prediou[i] = 0.f; return; }
    int mg;
    if (c == 1) {
        mg = d_lastg[i];
    } else {
        float best = 3.4e38f; int bi = 0;
        for (int g = 0; g < NG; g++) {
            float cv = d_cst[((size_t)(b * NG + g)) * NA + a];
            if (cv < best) { best = cv; bi = g; }   // first min on ties
        }
        mg = bi;
    }
    d_matched[i] = mg;
    d_prediou[i] = d_iou[((size_t)(b * NG + mg)) * NA + a];
}

__global__ void k_loss(const float* __restrict__ gtb, const int* __restrict__ gtc,
                       const float* __restrict__ f8, const float* __restrict__ f16,
                       const float* __restrict__ f32_) {
    __shared__ float s1[256], s2[256], s3[256];
    __shared__ int   s4[256];
    int tid = threadIdx.x;
    int i = blockIdx.x * blockDim.x + tid;
    float liou = 0.f, lobj = 0.f, lcls = 0.f; int nfg = 0;
    if (i < NB * NA) {
        int b = i / NA, a = i % NA;
        int mg = d_matched[i];
        bool fg = mg >= 0;
        float tgt = fg ? 0.9f : 0.f;
        float x = d_obj[i];
        lobj = fmaxf(x, 0.f) - x * tgt + log1pf(expf(-fabsf(x)));
        if (fg) {
            nfg = 1;
            const float* gb = gtb + ((size_t)b * NG + mg) * 4;
            float gx = gb[0], gy = gb[1], gw = gb[2], gh = gb[3];
            float4 pb = d_box[i];
            float tlx = fmaxf(pb.x - pb.z * 0.5f, gx - gw * 0.5f);
            float tly = fmaxf(pb.y - pb.w * 0.5f, gy - gh * 0.5f);
            float brx = fminf(pb.x + pb.z * 0.5f, gx + gw * 0.5f);
            float bry = fminf(pb.y + pb.w * 0.5f, gy + gh * 0.5f);
            bool en = (tlx < brx) && (tly < bry);
            float inter = en ? (brx - tlx) * (bry - tly) : 0.f;
            float uni = pb.z * pb.w + gw * gh - inter;
            float iou = inter / (uni + 1e-16f);
            liou = 1.f - iou * iou;
            // cls: softplus_sum - cls_lo[gc] * pred_iou
            int gc = gtc[b * NG + mg];
            const float* f; int hw, HW;
            if (a < A0)      { f = f8;   hw = a;      HW = 6400; }
            else if (a < A1) { f = f16;  hw = a - A0; HW = 1600; }
            else             { f = f32_; hw = a - A1; HW = 400;  }
            float cl = f[((size_t)b * (5 + NC) + 5 + gc) * HW + hw];
            lcls = d_sps[i] - cl * d_prediou[i];
        }
    }
    s1[tid] = liou; s2[tid] = lobj; s3[tid] = lcls; s4[tid] = nfg;
    __syncthreads();
    for (int s = 128; s > 0; s >>= 1) {
        if (tid < s) {
            s1[tid] += s1[tid + s]; s2[tid] += s2[tid + s];
            s3[tid] += s3[tid + s]; s4[tid] += s4[tid + s];
        }
        __syncthreads();
    }
    if (tid == 0) {
        atomicAdd(&d_acc[0], (double)s1[0]);
        atomicAdd(&d_acc[1], (double)s2[0]);
        atomicAdd(&d_acc[2], (double)s3[0]);
        atomicAdd(&d_acc[3], (double)s4[0]);
    }
}

__global__ void k_final(float* out) {
    double nfg = d_acc[3];
    if (nfg < 1.0) nfg = 1.0;
    out[0] = (float)((5.0 * d_acc[0] + d_acc[1] + d_acc[2]) / nfg);
}

// ---------------- launch ----------------
extern "C" void kernel_launch(void* const* d_in, const int* in_sizes, int n_in,
                              void* d_out, int out_size) {
    const float* f8   = (const float*)d_in[0];
    const float* f16  = (const float*)d_in[1];
    const float* f32_ = (const float*)d_in[2];
    const float* gtb  = (const float*)d_in[3];
    const int*   gtc  = (const int*)d_in[4];
    const int*   ngts = (const int*)d_in[5];
    float* out = (float*)d_out;

    const int NBA = NB * NA;
    const int T = 256;
    const int GBA = (NBA + T - 1) / T;

    k_zero<<<GBA, T>>>();
    k_decode<<<GBA, T>>>(f8, f16, f32_);
    k_fg<<<GBA, T>>>(gtb, ngts);
    k_cost<<<dim3((NA + T - 1) / T, NG, NB), T>>>(gtb, gtc, ngts);
    k_topk<<<dim3(NG, NB), T>>>(ngts);
    k_scatter<<<(NB * NG + T - 1) / T, T>>>(ngts);
    k_resolve<<<GBA, T>>>();
    k_loss<<<GBA, T>>>(gtb, gtc, f8, f16, f32_);
    k_final<<<1, 1>>>(out);
}

// round 2
// speedup vs baseline: 1.1912x; 1.1912x over previous
#include <cuda_runtime.h>
#include <cuda_bf16.h>
#include <math.h>

#define NB 32
#define NG 60
#define NC 80
#define NA 8400
#define A0 6400
#define A1 8000
#define TK 10

// ---------------- device scratch ----------------
__device__ float4 d_box[NB * NA];            // decoded boxes (cx,cy,w,h)
__device__ float  d_obj[NB * NA];            // objectness logits
__device__ float  d_b0s[NB * NA];            // sum_c -log(1-p)
__device__ float  d_dco[(size_t)NB * NC * NA]; // per-class (bce1-bce0), [b][c][a]
__device__ unsigned char d_fg[NB * NA];
__device__ float4 d_geo[NA];                 // (cxa, cya, st, 0)
__device__ int    d_pos[NB * NG * TK];
__device__ int    d_dynk[NB * NG];
__device__ int    d_cnt[NB * NA];
__device__ int    d_lastg[NB * NA];
__device__ int    d_matched[NB * NA];
__device__ float  d_prediou[NB * NA];
__device__ double d_acc[4]; // iou, obj, cls, nfg

// IoU between gt (gx,gy,gw,gh) and pred box pb — EXACT same expr/order as R0
__device__ __forceinline__ float iou_fn(float gx, float gy, float gw, float gh, float4 pb) {
    float tlx = fmaxf(gx - gw * 0.5f, pb.x - pb.z * 0.5f);
    float tly = fmaxf(gy - gh * 0.5f, pb.y - pb.w * 0.5f);
    float brx = fminf(gx + gw * 0.5f, pb.x + pb.z * 0.5f);
    float bry = fminf(gy + gh * 0.5f, pb.y + pb.w * 0.5f);
    bool en = (tlx < brx) && (tly < bry);
    float inter = en ? (brx - tlx) * (bry - tly) : 0.f;
    return inter / (gw * gh + pb.z * pb.w - inter + 1e-16f);
}

__device__ __forceinline__ float cost_fn(float gx, float gy, float gw, float gh,
                                         float iou, float cxa, float cya, float st,
                                         float b0s, float dco, unsigned char fgv, bool valid) {
    const float R = 2.5f;
    bool in_box = (cxa > gx - 0.5f * gw) && (cxa < gx + 0.5f * gw) &&
                  (cya > gy - 0.5f * gh) && (cya < gy + 0.5f * gh);
    bool in_ctr = (cxa > gx - R * st) && (cxa < gx + R * st) &&
                  (cya > gy - R * st) && (cya < gy + R * st);
    bool in_both = in_box && in_ctr;
    float cost = b0s + dco;
    cost += 3.0f * (-logf(iou + 1e-8f));
    cost += 100000.0f * (1.0f - (in_both ? 1.f : 0.f));
    cost += fgv ? 0.f : 1000000000.0f;
    cost += valid ? 0.f : 1000000000.0f;
    return cost;
}

// ---------------- kernels ----------------
__global__ void k_init() {
    int i = blockIdx.x * blockDim.x + threadIdx.x;
    if (i < NB * NA) d_cnt[i] = 0;
    if (i < 4) d_acc[i] = 0.0;
    if (i < NA) {
        float st; int hw, W;
        if (i < A0)      { st = 8.f;  hw = i;      W = 80; }
        else if (i < A1) { st = 16.f; hw = i - A0; W = 40; }
        else             { st = 32.f; hw = i - A1; W = 20; }
        int x = hw % W, y = hw / W;
        float4 ge;
        ge.x = (x + 0.5f) * st;
        ge.y = (y + 0.5f) * st;
        ge.z = st;
        ge.w = 0.f;
        d_geo[i] = ge;
    }
}

__global__ void k_decode(const float* __restrict__ f8,
                         const float* __restrict__ f16,
                         const float* __restrict__ f32_) {
    int i = blockIdx.x * blockDim.x + threadIdx.x;
    if (i >= NB * NA) return;
    int b = i / NA, a = i % NA;
    const float* f; int hw, HW, W; float st;
    if (a < A0)      { f = f8;   hw = a;      HW = 6400; W = 80; st = 8.f;  }
    else if (a < A1) { f = f16;  hw = a - A0; HW = 1600; W = 40; st = 16.f; }
    else             { f = f32_; hw = a - A1; HW = 400;  W = 20; st = 32.f; }
    float gx = (float)(hw % W), gy = (float)(hw / W);
    const float* base = f + (size_t)b * (5 + NC) * HW + hw;
    float tx = base[0 * HW], ty = base[(size_t)1 * HW];
    float tw = base[(size_t)2 * HW], th = base[(size_t)3 * HW];
    float to = base[(size_t)4 * HW];
    float4 bx;
    bx.x = (tx + gx) * st; bx.y = (ty + gy) * st;
    bx.z = expf(tw) * st;  bx.w = expf(th) * st;
    d_box[i] = bx;
    d_obj[i] = to;
    float so = 1.f / (1.f + expf(-to));
    float b0s = 0.f;
    for (int c = 0; c < NC; c++) {
        float x = base[(size_t)(5 + c) * HW];
        float sc = 1.f / (1.f + expf(-x));
        float p = sqrtf(sc * so);
        p = fminf(fmaxf(p, 1e-7f), 1.f - 1e-7f);
        float bce1 = -logf(p);
        float bce0 = -logf(1.f - p);
        b0s += bce0;
        d_dco[((size_t)b * NC + c) * NA + a] = bce1 - bce0;
    }
    d_b0s[i] = b0s;
}

__global__ void k_fg(const float* __restrict__ gtb, const int* __restrict__ ngts) {
    __shared__ float4 sgt[NG];
    int b = blockIdx.y;
    int n = ngts[b];
    if (threadIdx.x < NG) {
        const float* gb = gtb + ((size_t)b * NG + threadIdx.x) * 4;
        sgt[threadIdx.x] = make_float4(gb[0], gb[1], gb[2], gb[3]);
    }
    __syncthreads();
    int a = blockIdx.x * blockDim.x + threadIdx.x;
    if (a >= NA) return;
    float4 ge = d_geo[a];
    float cxa = ge.x, cya = ge.y, st = ge.z;
    const float R = 2.5f;
    bool fg = false;
    for (int g = 0; g < n; g++) {
        float4 gb = sgt[g];
        bool in_box = (cxa > gb.x - 0.5f * gb.z) && (cxa < gb.x + 0.5f * gb.z) &&
                      (cya > gb.y - 0.5f * gb.w) && (cya < gb.y + 0.5f * gb.w);
        bool in_ctr = (cxa > gb.x - R * st) && (cxa < gb.x + R * st) &&
                      (cya > gb.y - R * st) && (cya < gb.y + R * st);
        fg = fg || in_box || in_ctr;
    }
    d_fg[b * NA + a] = fg ? 1 : 0;
}

// Fused cost+iou computation + single-pass top-k per (b,g)
__global__ void k_assign(const float* __restrict__ gtb, const int* __restrict__ gtc,
                         const int* __restrict__ ngts) {
    int g = blockIdx.x, b = blockIdx.y, tid = threadIdx.x;
    if (g >= ngts[b]) return;

    __shared__ float s_lv[256 * TK];
    __shared__ int   s_li[256 * TK];
    __shared__ int   s_head[256];

    const float* gb = gtb + ((size_t)b * NG + g) * 4;
    float gx = gb[0], gy = gb[1], gw = gb[2], gh = gb[3];
    int gc = gtc[b * NG + g];

    const float4* boxp = d_box + b * NA;
    const float* b0p = d_b0s + b * NA;
    const unsigned char* fgp = d_fg + b * NA;
    const float* dcop = d_dco + ((size_t)b * NC + gc) * NA;

    // local sorted top-10 lists (registers)
    float iv[TK]; int ii[TK];   // max list of iou*fg
    float cv[TK]; int ci[TK];   // min list of cost
#pragma unroll
    for (int k = 0; k < TK; k++) { iv[k] = -1.f; ii[k] = 0x7fffffff; cv[k] = 3.4e38f; ci[k] = 0x7fffffff; }

    for (int a = tid; a < NA; a += 256) {
        float4 pb = boxp[a];
        float iou = iou_fn(gx, gy, gw, gh, pb);
        unsigned char fgv = fgp[a];
        float key = fgv ? iou : 0.f;
        // max-insert (iou*fg)
        if (key > iv[TK - 1] || (key == iv[TK - 1] && a < ii[TK - 1])) {
            iv[TK - 1] = key; ii[TK - 1] = a;
#pragma unroll
            for (int k = TK - 1; k > 0; k--) {
                if (iv[k] > iv[k - 1] || (iv[k] == iv[k - 1] && ii[k] < ii[k - 1])) {
                    float tv = iv[k]; iv[k] = iv[k - 1]; iv[k - 1] = tv;
                    int ti = ii[k]; ii[k] = ii[k - 1]; ii[k - 1] = ti;
                }
            }
        }
        float4 ge = d_geo[a];
        float cost = cost_fn(gx, gy, gw, gh, iou, ge.x, ge.y, ge.z, b0p[a], dcop[a], fgv, true);
        // min-insert (cost)
        if (cost < cv[TK - 1] || (cost == cv[TK - 1] && a < ci[TK - 1])) {
            cv[TK - 1] = cost; ci[TK - 1] = a;
#pragma unroll
            for (int k = TK - 1; k > 0; k--) {
                if (cv[k] < cv[k - 1] || (cv[k] == cv[k - 1] && ci[k] < ci[k - 1])) {
                    float tv = cv[k]; cv[k] = cv[k - 1]; cv[k - 1] = tv;
                    int ti = ci[k]; ci[k] = ci[k - 1]; ci[k - 1] = ti;
                }
            }
        }
    }

    // ---- merge iou lists (max, tie -> smaller index): only need the sum ----
#pragma unroll
    for (int k = 0; k < TK; k++) { s_lv[tid * TK + k] = iv[k]; s_li[tid * TK + k] = ii[k]; }
    __syncthreads();
    if (tid < 32) {
        for (int l = tid; l < 256; l += 32) s_head[l] = 0;
        __syncwarp();
        float ksum = 0.f;
        for (int r = 0; r < TK; r++) {
            float bv = -2.f; int bi = 0x7fffffff; int bl = -1;
            for (int k = 0; k < 8; k++) {
                int l = tid + 32 * k;
                int hd = s_head[l];
                float v = s_lv[l * TK + hd]; int idx = s_li[l * TK + hd];
                if (v > bv || (v == bv && idx < bi)) { bv = v; bi = idx; bl = l; }
            }
            for (int o = 16; o; o >>= 1) {
                float ov = __shfl_xor_sync(0xffffffffu, bv, o);
                int oi = __shfl_xor_sync(0xffffffffu, bi, o);
                int ol = __shfl_xor_sync(0xffffffffu, bl, o);
                if (ov > bv || (ov == bv && oi < bi)) { bv = ov; bi = oi; bl = ol; }
            }
            ksum += bv;
            if (tid == 0) s_head[bl]++;
            __syncwarp();
        }
        if (tid == 0) {
            int dk = (int)ksum;
            if (dk < 1) dk = 1;
            d_dynk[b * NG + g] = dk;
        }
    }
    __syncthreads();

    // ---- merge cost lists (min, tie -> smaller index): write pos[0..9] ----
#pragma unroll
    for (int k = 0; k < TK; k++) { s_lv[tid * TK + k] = cv[k]; s_li[tid * TK + k] = ci[k]; }
    __syncthreads();
    if (tid < 32) {
        for (int l = tid; l < 256; l += 32) s_head[l] = 0;
        __syncwarp();
        for (int r = 0; r < TK; r++) {
            float bv = 3.5e38f; int bi = 0x7fffffff; int bl = -1;
            for (int k = 0; k < 8; k++) {
                int l = tid + 32 * k;
                int hd = s_head[l];
                float v = s_lv[l * TK + hd]; int idx = s_li[l * TK + hd];
                if (v < bv || (v == bv && idx < bi)) { bv = v; bi = idx; bl = l; }
            }
            for (int o = 16; o; o >>= 1) {
                float ov = __shfl_xor_sync(0xffffffffu, bv, o);
                int oi = __shfl_xor_sync(0xffffffffu, bi, o);
                int ol = __shfl_xor_sync(0xffffffffu, bl, o);
                if (ov < bv || (ov == bv && oi < bi)) { bv = ov; bi = oi; bl = ol; }
            }
            if (tid == 0) {
                d_pos[(b * NG + g) * TK + r] = bi;
                s_head[bl]++;
            }
            __syncwarp();
        }
    }
}

__global__ void k_scatter(const int* __restrict__ ngts) {
    int i = blockIdx.x * blockDim.x + threadIdx.x;
    if (i >= NB * NG) return;
    int b = i / NG, g = i % NG;
    if (g >= ngts[b]) return;
    int dk = d_dynk[i];
    for (int k = 0; k < dk; k++) {
        int a = d_pos[i * TK + k];
        atomicAdd(&d_cnt[b * NA + a], 1);
        d_lastg[b * NA + a] = g;
    }
}

__global__ void k_resolve(const float* __restrict__ gtb, const int* __restrict__ gtc,
                          const int* __restrict__ ngts) {
    int i = blockIdx.x * blockDim.x + threadIdx.x;
    if (i >= NB * NA) return;
    int b = i / NA, a = i % NA;
    int c = d_cnt[i];
    if (c == 0) { d_matched[i] = -1; d_prediou[i] = 0.f; return; }
    int mg;
    float4 pb = d_box[i];
    if (c == 1) {
        mg = d_lastg[i];
    } else {
        int n = ngts[b];
        float4 ge = d_geo[a];
        float b0s = d_b0s[i];
        unsigned char fgv = d_fg[i];
        float best = 3.5e38f; int bi = 0;
        for (int g = 0; g < NG; g++) {
            const float* gb = gtb + ((size_t)b * NG + g) * 4;
            float gx = gb[0], gy = gb[1], gw = gb[2], gh = gb[3];
            int gc = gtc[b * NG + g];
            float iou = iou_fn(gx, gy, gw, gh, pb);
            float dco = d_dco[((size_t)b * NC + gc) * NA + a];
            float cv = cost_fn(gx, gy, gw, gh, iou, ge.x, ge.y, ge.z, b0s, dco, fgv, g < n);
            if (cv < best) { best = cv; bi = g; }  // first min on ties
        }
        mg = bi;
    }
    d_matched[i] = mg;
    const float* gb = gtb + ((size_t)b * NG + mg) * 4;
    d_prediou[i] = iou_fn(gb[0], gb[1], gb[2], gb[3], pb);
}

__global__ void k_loss(const float* __restrict__ gtb, const int* __restrict__ gtc,
                       const float* __restrict__ f8, const float* __restrict__ f16,
                       const float* __restrict__ f32_) {
    __shared__ float s1[256], s2[256], s3[256];
    __shared__ int   s4[256];
    int tid = threadIdx.x;
    int i = blockIdx.x * blockDim.x + tid;
    float liou = 0.f, lobj = 0.f, lcls = 0.f; int nfg = 0;
    if (i < NB * NA) {
        int b = i / NA, a = i % NA;
        int mg = d_matched[i];
        bool fg = mg >= 0;
        float tgt = fg ? 0.9f : 0.f;
        float x = d_obj[i];
        lobj = fmaxf(x, 0.f) - x * tgt + log1pf(expf(-fabsf(x)));
        if (fg) {
            nfg = 1;
            const float* gb = gtb + ((size_t)b * NG + mg) * 4;
            float gx = gb[0], gy = gb[1], gw = gb[2], gh = gb[3];
            float4 pb = d_box[i];
            float tlx = fmaxf(pb.x - pb.z * 0.5f, gx - gw * 0.5f);
            float tly = fmaxf(pb.y - pb.w * 0.5f, gy - gh * 0.5f);
            float brx = fminf(pb.x + pb.z * 0.5f, gx + gw * 0.5f);
            float bry = fminf(pb.y + pb.w * 0.5f, gy + gh * 0.5f);
            bool en = (tlx < brx) && (tly < bry);
            float inter = en ? (brx - tlx) * (bry - tly) : 0.f;
            float uni = pb.z * pb.w + gw * gh - inter;
            float iou = inter / (uni + 1e-16f);
            liou = 1.f - iou * iou;
            // cls: sum_c softplus(x_c) - x_gc * pred_iou, computed on the fly
            int gc = gtc[b * NG + mg];
            const float* f; int hw, HW;
            if (a < A0)      { f = f8;   hw = a;      HW = 6400; }
            else if (a < A1) { f = f16;  hw = a - A0; HW = 1600; }
            else             { f = f32_; hw = a - A1; HW = 400;  }
            const float* base = f + (size_t)b * (5 + NC) * HW + hw;
            float sps = 0.f;
            for (int c = 0; c < NC; c++) {
                float xc = base[(size_t)(5 + c) * HW];
                sps += fmaxf(xc, 0.f) + log1pf(expf(-fabsf(xc)));
            }
            float cl = base[(size_t)(5 + gc) * HW];
            lcls = sps - cl * d_prediou[i];
        }
    }
    s1[tid] = liou; s2[tid] = lobj; s3[tid] = lcls; s4[tid] = nfg;
    __syncthreads();
    for (int s = 128; s > 0; s >>= 1) {
        if (tid < s) {
            s1[tid] += s1[tid + s]; s2[tid] += s2[tid + s];
            s3[tid] += s3[tid + s]; s4[tid] += s4[tid + s];
        }
        __syncthreads();
    }
    if (tid == 0) {
        atomicAdd(&d_acc[0], (double)s1[0]);
        atomicAdd(&d_acc[1], (double)s2[0]);
        atomicAdd(&d_acc[2], (double)s3[0]);
        atomicAdd(&d_acc[3], (double)s4[0]);
    }
}

__global__ void k_final(float* out) {
    double nfg = d_acc[3];
    if (nfg < 1.0) nfg = 1.0;
    out[0] = (float)((5.0 * d_acc[0] + d_acc[1] + d_acc[2]) / nfg);
}

// ---------------- launch ----------------
extern "C" void kernel_launch(void* const* d_in, const int* in_sizes, int n_in,
                              void* d_out, int out_size) {
    const float* f8   = (const float*)d_in[0];
    const float* f16  = (const float*)d_in[1];
    const float* f32_ = (const float*)d_in[2];
    const float* gtb  = (const float*)d_in[3];
    const int*   gtc  = (const int*)d_in[4];
    const int*   ngts = (const int*)d_in[5];
    float* out = (float*)d_out;

    const int NBA = NB * NA;
    const int T = 256;
    const int GBA = (NBA + T - 1) / T;

    k_init<<<GBA, T>>>();
    k_decode<<<GBA, T>>>(f8, f16, f32_);
    k_fg<<<dim3((NA + T - 1) / T, NB), T>>>(gtb, ngts);
    k_assign<<<dim3(NG, NB), T>>>(gtb, gtc, ngts);
    k_scatter<<<(NB * NG + T - 1) / T, T>>>(ngts);
    k_resolve<<<GBA, T>>>(gtb, gtc, ngts);
    k_loss<<<GBA, T>>>(gtb, gtc, f8, f16, f32_);
    k_final<<<1, 1>>>(out);
}

// round 3
// speedup vs baseline: 1.4418x; 1.2104x over previous
#include <cuda_runtime.h>
#include <cuda_bf16.h>
#include <math.h>

#define NB 32
#define NG 60
#define NC 80
#define NA 8400
#define A0 6400
#define A1 8000
#define TK 10

// ---------------- device scratch ----------------
__device__ float4 d_box[NB * NA];            // decoded boxes by anchor
__device__ float  d_obj[NB * NA];            // objectness logits
__device__ unsigned char d_fg[NB * NA];
__device__ float4 d_geo[NA];                 // (cxa, cya, st, 0)
__device__ int    d_fglist[NB * NA];         // compacted fg anchor ids (ascending)
__device__ int    d_fgpos[NB * NA];          // a -> j (valid only for fg a)
__device__ int    d_fgcnt[NB];
__device__ float4 d_boxC[NB * NA];           // compacted boxes
__device__ float4 d_geoC[NB * NA];           // compacted geo
__device__ float  d_b0sC[NB * NA];           // compacted sum_c -log(1-p)
__device__ float  d_spsC[NB * NA];           // compacted sum_c softplus
__device__ float  d_dcoC[(size_t)NB * NC * NA]; // compacted (bce1-bce0): [b][c][j]
__device__ int    d_pos[NB * NG * TK];
__device__ int    d_dynk[NB * NG];
__device__ int    d_cnt[NB * NA];
__device__ int    d_lastg[NB * NA];
__device__ int    d_matched[NB * NA];
__device__ float  d_prediou[NB * NA];
__device__ double d_acc[4];

__device__ __forceinline__ float iou_fn(float gx, float gy, float gw, float gh, float4 pb) {
    float tlx = fmaxf(gx - gw * 0.5f, pb.x - pb.z * 0.5f);
    float tly = fmaxf(gy - gh * 0.5f, pb.y - pb.w * 0.5f);
    float brx = fminf(gx + gw * 0.5f, pb.x + pb.z * 0.5f);
    float bry = fminf(gy + gh * 0.5f, pb.y + pb.w * 0.5f);
    bool en = (tlx < brx) && (tly < bry);
    float inter = en ? (brx - tlx) * (bry - tly) : 0.f;
    return inter / (gw * gh + pb.z * pb.w - inter + 1e-16f);
}

__device__ __forceinline__ float cost_fn(float gx, float gy, float gw, float gh,
                                         float iou, float cxa, float cya, float st,
                                         float b0s, float dco, bool fgv, bool valid) {
    const float R = 2.5f;
    bool in_box = (cxa > gx - 0.5f * gw) && (cxa < gx + 0.5f * gw) &&
                  (cya > gy - 0.5f * gh) && (cya < gy + 0.5f * gh);
    bool in_ctr = (cxa > gx - R * st) && (cxa < gx + R * st) &&
                  (cya > gy - R * st) && (cya < gy + R * st);
    bool in_both = in_box && in_ctr;
    float cost = b0s + dco;
    cost += 3.0f * (-logf(iou + 1e-8f));
    cost += 100000.0f * (1.0f - (in_both ? 1.f : 0.f));
    cost += fgv ? 0.f : 1000000000.0f;
    cost += valid ? 0.f : 1000000000.0f;
    return cost;
}

// ---------------- kernels ----------------
__global__ void k_init() {
    int i = blockIdx.x * blockDim.x + threadIdx.x;
    if (i < NB * NA) d_cnt[i] = 0;
    if (i < 4) d_acc[i] = 0.0;
    if (i < NA) {
        float st; int hw, W;
        if (i < A0)      { st = 8.f;  hw = i;      W = 80; }
        else if (i < A1) { st = 16.f; hw = i - A0; W = 40; }
        else             { st = 32.f; hw = i - A1; W = 20; }
        int x = hw % W, y = hw / W;
        d_geo[i] = make_float4((x + 0.5f) * st, (y + 0.5f) * st, st, 0.f);
    }
}

// boxes + obj only (no class loop)
__global__ void k_decode(const float* __restrict__ f8,
                         const float* __restrict__ f16,
                         const float* __restrict__ f32_) {
    int i = blockIdx.x * blockDim.x + threadIdx.x;
    if (i >= NB * NA) return;
    int b = i / NA, a = i % NA;
    const float* f; int hw, HW, W; float st;
    if (a < A0)      { f = f8;   hw = a;      HW = 6400; W = 80; st = 8.f;  }
    else if (a < A1) { f = f16;  hw = a - A0; HW = 1600; W = 40; st = 16.f; }
    else             { f = f32_; hw = a - A1; HW = 400;  W = 20; st = 32.f; }
    float gx = (float)(hw % W), gy = (float)(hw / W);
    const float* base = f + (size_t)b * (5 + NC) * HW + hw;
    float tx = base[0 * HW], ty = base[(size_t)1 * HW];
    float tw = base[(size_t)2 * HW], th = base[(size_t)3 * HW];
    float to = base[(size_t)4 * HW];
    d_box[i] = make_float4((tx + gx) * st, (ty + gy) * st, expf(tw) * st, expf(th) * st);
    d_obj[i] = to;
}

__global__ void k_fg(const float* __restrict__ gtb, const int* __restrict__ ngts) {
    __shared__ float4 sgt[NG];
    int b = blockIdx.y;
    int n = ngts[b];
    if (threadIdx.x < NG) {
        const float* gb = gtb + ((size_t)b * NG + threadIdx.x) * 4;
        sgt[threadIdx.x] = make_float4(gb[0], gb[1], gb[2], gb[3]);
    }
    __syncthreads();
    int a = blockIdx.x * blockDim.x + threadIdx.x;
    if (a >= NA) return;
    float4 ge = d_geo[a];
    float cxa = ge.x, cya = ge.y, st = ge.z;
    const float R = 2.5f;
    bool fg = false;
    for (int g = 0; g < n; g++) {
        float4 gb = sgt[g];
        bool in_box = (cxa > gb.x - 0.5f * gb.z) && (cxa < gb.x + 0.5f * gb.z) &&
                      (cya > gb.y - 0.5f * gb.w) && (cya < gb.y + 0.5f * gb.w);
        bool in_ctr = (cxa > gb.x - R * st) && (cxa < gb.x + R * st) &&
                      (cya > gb.y - R * st) && (cya < gb.y + R * st);
        fg = fg || in_box || in_ctr;
    }
    d_fg[b * NA + a] = fg ? 1 : 0;
}

// one block per b: ordered compaction of fg anchors + copy box/geo compacted
__global__ void k_compact() {
    __shared__ int swcnt[8];
    __shared__ int swoff[8];
    __shared__ int sbase;
    int b = blockIdx.x, tid = threadIdx.x;
    int warp = tid >> 5, lane = tid & 31;
    if (tid == 0) sbase = 0;
    __syncthreads();
    for (int t = 0; t < (NA + 255) / 256; t++) {
        int a = t * 256 + tid;
        bool flag = (a < NA) && d_fg[b * NA + a];
        unsigned bal = __ballot_sync(0xffffffffu, flag);
        int intra = __popc(bal & ((1u << lane) - 1u));
        if (lane == 0) swcnt[warp] = __popc(bal);
        __syncthreads();
        if (tid == 0) {
            int s = 0;
            for (int w = 0; w < 8; w++) { swoff[w] = s; s += swcnt[w]; }
            swcnt[0] = s; // total
        }
        __syncthreads();
        if (flag) {
            int j = sbase + swoff[warp] + intra;
            d_fglist[b * NA + j] = a;
            d_fgpos[b * NA + a] = j;
            d_boxC[b * NA + j] = d_box[b * NA + a];
            d_geoC[b * NA + j] = d_geo[a];
        }
        __syncthreads();
        if (tid == 0) sbase += swcnt[0];
        __syncthreads();
    }
    if (tid == 0) d_fgcnt[b] = sbase;
}

// class BCE precompute, fg anchors only, compacted layout
__global__ void k_clsprep(const float* __restrict__ f8, const float* __restrict__ f16,
                          const float* __restrict__ f32_) {
    int b = blockIdx.y;
    int j = blockIdx.x * blockDim.x + threadIdx.x;
    if (j >= d_fgcnt[b]) return;
    int a = d_fglist[b * NA + j];
    const float* f; int hw, HW;
    if (a < A0)      { f = f8;   hw = a;      HW = 6400; }
    else if (a < A1) { f = f16;  hw = a - A0; HW = 1600; }
    else             { f = f32_; hw = a - A1; HW = 400;  }
    const float* base = f + (size_t)b * (5 + NC) * HW + hw;
    float to = d_obj[b * NA + a];
    float so = 1.f / (1.f + expf(-to));
    float b0s = 0.f, sps = 0.f;
    for (int c = 0; c < NC; c++) {
        float x = base[(size_t)(5 + c) * HW];
        float sc = 1.f / (1.f + expf(-x));
        float p = sqrtf(sc * so);
        p = fminf(fmaxf(p, 1e-7f), 1.f - 1e-7f);
        float bce1 = -logf(p);
        float bce0 = -logf(1.f - p);
        b0s += bce0;
        d_dcoC[((size_t)b * NC + c) * NA + j] = bce1 - bce0;
        sps += fmaxf(x, 0.f) + log1pf(expf(-fabsf(x)));
    }
    d_b0sC[b * NA + j] = b0s;
    d_spsC[b * NA + j] = sps;
}

// fused cost+iou + single-pass top-k over the compact fg list
__global__ void k_assign(const float* __restrict__ gtb, const int* __restrict__ gtc,
                         const int* __restrict__ ngts) {
    int g = blockIdx.x, b = blockIdx.y, tid = threadIdx.x;
    if (g >= ngts[b]) return;

    __shared__ float s_lv[256 * TK];
    __shared__ int   s_li[256 * TK];
    __shared__ int   s_head[256];

    const float* gb = gtb + ((size_t)b * NG + g) * 4;
    float gx = gb[0], gy = gb[1], gw = gb[2], gh = gb[3];
    int gc = gtc[b * NG + g];
    int cnt = d_fgcnt[b];

    const float4* boxp = d_boxC + b * NA;
    const float4* geop = d_geoC + b * NA;
    const float* b0p = d_b0sC + b * NA;
    const float* dcop = d_dcoC + ((size_t)b * NC + gc) * NA;

    float iv[TK]; int ii[TK];
    float cv[TK]; int ci[TK];
#pragma unroll
    for (int k = 0; k < TK; k++) { iv[k] = -1.f; ii[k] = 0x7fffffff; cv[k] = 3.4e38f; ci[k] = 0x7fffffff; }

    for (int j = tid; j < cnt; j += 256) {
        float4 pb = boxp[j];
        float iou = iou_fn(gx, gy, gw, gh, pb);
        // max-insert (iou; all candidates are fg)
        if (iou > iv[TK - 1] || (iou == iv[TK - 1] && j < ii[TK - 1])) {
            iv[TK - 1] = iou; ii[TK - 1] = j;
#pragma unroll
            for (int k = TK - 1; k > 0; k--) {
                if (iv[k] > iv[k - 1] || (iv[k] == iv[k - 1] && ii[k] < ii[k - 1])) {
                    float tv = iv[k]; iv[k] = iv[k - 1]; iv[k - 1] = tv;
                    int ti = ii[k]; ii[k] = ii[k - 1]; ii[k - 1] = ti;
                }
            }
        }
        float4 ge = geop[j];
        float cost = cost_fn(gx, gy, gw, gh, iou, ge.x, ge.y, ge.z, b0p[j], dcop[j], true, true);
        if (cost < cv[TK - 1] || (cost == cv[TK - 1] && j < ci[TK - 1])) {
            cv[TK - 1] = cost; ci[TK - 1] = j;
#pragma unroll
            for (int k = TK - 1; k > 0; k--) {
                if (cv[k] < cv[k - 1] || (cv[k] == cv[k - 1] && ci[k] < ci[k - 1])) {
                    float tv = cv[k]; cv[k] = cv[k - 1]; cv[k - 1] = tv;
                    int ti = ci[k]; ci[k] = ci[k - 1]; ci[k - 1] = ti;
                }
            }
        }
    }

    // ---- merge iou lists (max, tie -> smaller j): only the descending sum ----
#pragma unroll
    for (int k = 0; k < TK; k++) { s_lv[tid * TK + k] = iv[k]; s_li[tid * TK + k] = ii[k]; }
    __syncthreads();
    if (tid < 32) {
        for (int l = tid; l < 256; l += 32) s_head[l] = 0;
        __syncwarp();
        float ksum = 0.f;
        for (int r = 0; r < TK; r++) {
            float bv = -2.f; int bi = 0x7fffffff; int bl = -1;
            for (int k = 0; k < 8; k++) {
                int l = tid + 32 * k;
                int hd = s_head[l];
                float v = s_lv[l * TK + hd]; int idx = s_li[l * TK + hd];
                if (v > bv || (v == bv && idx < bi)) { bv = v; bi = idx; bl = l; }
            }
            for (int o = 16; o; o >>= 1) {
                float ov = __shfl_xor_sync(0xffffffffu, bv, o);
                int oi = __shfl_xor_sync(0xffffffffu, bi, o);
                int ol = __shfl_xor_sync(0xffffffffu, bl, o);
                if (ov > bv || (ov == bv && oi < bi)) { bv = ov; bi = oi; bl = ol; }
            }
            ksum += fmaxf(bv, 0.f);   // sentinel -1 contributes 0 like reference's zero pad
            if (tid == 0) s_head[bl]++;
            __syncwarp();
        }
        if (tid == 0) {
            int dk = (int)ksum;
            if (dk < 1) dk = 1;
            d_dynk[b * NG + g] = dk;
        }
    }
    __syncthreads();

    // ---- merge cost lists (min, tie -> smaller j): write pos as anchor ids ----
#pragma unroll
    for (int k = 0; k < TK; k++) { s_lv[tid * TK + k] = cv[k]; s_li[tid * TK + k] = ci[k]; }
    __syncthreads();
    if (tid < 32) {
        for (int l = tid; l < 256; l += 32) s_head[l] = 0;
        __syncwarp();
        for (int r = 0; r < TK; r++) {
            float bv = 3.5e38f; int bi = 0x7fffffff; int bl = -1;
            for (int k = 0; k < 8; k++) {
                int l = tid + 32 * k;
                int hd = s_head[l];
                float v = s_lv[l * TK + hd]; int idx = s_li[l * TK + hd];
                if (v < bv || (v == bv && idx < bi)) { bv = v; bi = idx; bl = l; }
            }
            for (int o = 16; o; o >>= 1) {
                float ov = __shfl_xor_sync(0xffffffffu, bv, o);
                int oi = __shfl_xor_sync(0xffffffffu, bi, o);
                int ol = __shfl_xor_sync(0xffffffffu, bl, o);
                if (ov < bv || (ov == bv && oi < bi)) { bv = ov; bi = oi; bl = ol; }
            }
            if (tid == 0) {
                d_pos[(b * NG + g) * TK + r] = d_fglist[b * NA + bi];
                s_head[bl]++;
            }
            __syncwarp();
        }
    }
}

__global__ void k_scatter(const int* __restrict__ ngts) {
    int i = blockIdx.x * blockDim.x + threadIdx.x;
    if (i >= NB * NG) return;
    int b = i / NG, g = i % NG;
    if (g >= ngts[b]) return;
    int dk = d_dynk[i];
    for (int k = 0; k < dk; k++) {
        int a = d_pos[i * TK + k];
        atomicAdd(&d_cnt[b * NA + a], 1);
        d_lastg[b * NA + a] = g;
    }
}

__global__ void k_resolve(const float* __restrict__ gtb, const int* __restrict__ gtc,
                          const int* __restrict__ ngts) {
    int i = blockIdx.x * blockDim.x + threadIdx.x;
    if (i >= NB * NA) return;
    int b = i / NA, a = i % NA;
    int c = d_cnt[i];
    if (c == 0) { d_matched[i] = -1; d_prediou[i] = 0.f; return; }
    int mg;
    float4 pb = d_box[i];
    if (c == 1) {
        mg = d_lastg[i];
    } else {
        int n = ngts[b];
        int j = d_fgpos[i];              // matched anchors are always fg
        float4 ge = d_geo[a];
        float b0s = d_b0sC[b * NA + j];
        float best = 3.5e38f; int bi = 0;
        for (int g = 0; g < NG; g++) {
            const float* gb = gtb + ((size_t)b * NG + g) * 4;
            float gx = gb[0], gy = gb[1], gw = gb[2], gh = gb[3];
            int gc = gtc[b * NG + g];
            float iou = iou_fn(gx, gy, gw, gh, pb);
            float dco = d_dcoC[((size_t)b * NC + gc) * NA + j];
            float cv = cost_fn(gx, gy, gw, gh, iou, ge.x, ge.y, ge.z, b0s, dco, true, g < n);
            if (cv < best) { best = cv; bi = g; }
        }
        mg = bi;
    }
    d_matched[i] = mg;
    const float* gb = gtb + ((size_t)b * NG + mg) * 4;
    d_prediou[i] = iou_fn(gb[0], gb[1], gb[2], gb[3], pb);
}

__global__ void k_loss(const float* __restrict__ gtb, const int* __restrict__ gtc,
                       const float* __restrict__ f8, const float* __restrict__ f16,
                       const float* __restrict__ f32_) {
    __shared__ float s1[256], s2[256], s3[256];
    __shared__ int   s4[256];
    int tid = threadIdx.x;
    int i = blockIdx.x * blockDim.x + tid;
    float liou = 0.f, lobj = 0.f, lcls = 0.f; int nfg = 0;
    if (i < NB * NA) {
        int b = i / NA, a = i % NA;
        int mg = d_matched[i];
        bool fg = mg >= 0;
        float tgt = fg ? 0.9f : 0.f;
        float x = d_obj[i];
        lobj = fmaxf(x, 0.f) - x * tgt + log1pf(expf(-fabsf(x)));
        if (fg) {
            nfg = 1;
            const float* gb = gtb + ((size_t)b * NG + mg) * 4;
            float gx = gb[0], gy = gb[1], gw = gb[2], gh = gb[3];
            float4 pb = d_box[i];
            float tlx = fmaxf(pb.x - pb.z * 0.5f, gx - gw * 0.5f);
            float tly = fmaxf(pb.y - pb.w * 0.5f, gy - gh * 0.5f);
            float brx = fminf(pb.x + pb.z * 0.5f, gx + gw * 0.5f);
            float bry = fminf(pb.y + pb.w * 0.5f, gy + gh * 0.5f);
            bool en = (tlx < brx) && (tly < bry);
            float inter = en ? (brx - tlx) * (bry - tly) : 0.f;
            float uni = pb.z * pb.w + gw * gh - inter;
            float iou = inter / (uni + 1e-16f);
            liou = 1.f - iou * iou;
            int gc = gtc[b * NG + mg];
            const float* f; int hw, HW;
            if (a < A0)      { f = f8;   hw = a;      HW = 6400; }
            else if (a < A1) { f = f16;  hw = a - A0; HW = 1600; }
            else             { f = f32_; hw = a - A1; HW = 400;  }
            float cl = f[((size_t)b * (5 + NC) + 5 + gc) * HW + hw];
            lcls = d_spsC[b * NA + d_fgpos[i]] - cl * d_prediou[i];
        }
    }
    s1[tid] = liou; s2[tid] = lobj; s3[tid] = lcls; s4[tid] = nfg;
    __syncthreads();
    for (int s = 128; s > 0; s >>= 1) {
        if (tid < s) {
            s1[tid] += s1[tid + s]; s2[tid] += s2[tid + s];
            s3[tid] += s3[tid + s]; s4[tid] += s4[tid + s];
        }
        __syncthreads();
    }
    if (tid == 0) {
        atomicAdd(&d_acc[0], (double)s1[0]);
        atomicAdd(&d_acc[1], (double)s2[0]);
        atomicAdd(&d_acc[2], (double)s3[0]);
        atomicAdd(&d_acc[3], (double)s4[0]);
    }
}

__global__ void k_final(float* out) {
    double nfg = d_acc[3];
    if (nfg < 1.0) nfg = 1.0;
    out[0] = (float)((5.0 * d_acc[0] + d_acc[1] + d_acc[2]) / nfg);
}

// ---------------- launch ----------------
extern "C" void kernel_launch(void* const* d_in, const int* in_sizes, int n_in,
                              void* d_out, int out_size) {
    const float* f8   = (const float*)d_in[0];
    const float* f16  = (const float*)d_in[1];
    const float* f32_ = (const float*)d_in[2];
    const float* gtb  = (const float*)d_in[3];
    const int*   gtc  = (const int*)d_in[4];
    const int*   ngts = (const int*)d_in[5];
    float* out = (float*)d_out;

    const int NBA = NB * NA;
    const int T = 256;
    const int GBA = (NBA + T - 1) / T;
    const int GA = (NA + T - 1) / T;

    k_init<<<GBA, T>>>();
    k_decode<<<GBA, T>>>(f8, f16, f32_);
    k_fg<<<dim3(GA, NB), T>>>(gtb, ngts);
    k_compact<<<NB, T>>>();
    k_clsprep<<<dim3(GA, NB), T>>>(f8, f16, f32_);
    k_assign<<<dim3(NG, NB), T>>>(gtb, gtc, ngts);
    k_scatter<<<(NB * NG + T - 1) / T, T>>>(ngts);
    k_resolve<<<GBA, T>>>(gtb, gtc, ngts);
    k_loss<<<GBA, T>>>(gtb, gtc, f8, f16, f32_);
    k_final<<<1, 1>>>(out);
}

// round 4
// speedup vs baseline: 1.6344x; 1.1336x over previous
#include <cuda_runtime.h>
#include <cuda_bf16.h>
#include <math.h>

#define NB 32
#define NG 60
#define NC 80
#define NA 8400
#define A0 6400
#define A1 8000
#define TK 10
#define NCH 33   // ceil(NA/256)

// ---------------- device scratch ----------------
__device__ float4 d_box[NB * NA];
__device__ float  d_obj[NB * NA];
__device__ unsigned char d_fg[NB * NA];
__device__ float4 d_geo[NA];
__device__ int    d_ccnt[NB * NCH];          // per-chunk fg counts
__device__ int    d_coff[NB * NCH];          // exclusive scan of counts
__device__ int    d_fglist[NB * NA];
__device__ int    d_fgpos[NB * NA];
__device__ int    d_fgcnt[NB];
__device__ float4 d_boxC[NB * NA];
__device__ float4 d_geoC[NB * NA];
__device__ float  d_b0sC[NB * NA];
__device__ float  d_spsC[NB * NA];
__device__ float  d_dcoC[(size_t)NB * NC * NA];
__device__ int    d_pos[NB * NG * TK];
__device__ int    d_dynk[NB * NG];
__device__ int    d_cnt[NB * NA];
__device__ int    d_lastg[NB * NA];
__device__ int    d_matched[NB * NA];
__device__ float  d_prediou[NB * NA];
__device__ double d_acc[4];

__device__ __forceinline__ float iou_fn(float gx, float gy, float gw, float gh, float4 pb) {
    float tlx = fmaxf(gx - gw * 0.5f, pb.x - pb.z * 0.5f);
    float tly = fmaxf(gy - gh * 0.5f, pb.y - pb.w * 0.5f);
    float brx = fminf(gx + gw * 0.5f, pb.x + pb.z * 0.5f);
    float bry = fminf(gy + gh * 0.5f, pb.y + pb.w * 0.5f);
    bool en = (tlx < brx) && (tly < bry);
    float inter = en ? (brx - tlx) * (bry - tly) : 0.f;
    return inter / (gw * gh + pb.z * pb.w - inter + 1e-16f);
}

// c0 = -logf(1e-8f) evaluated with device logf (bit-identical to inline path)
__device__ __forceinline__ float cost_fn(float gx, float gy, float gw, float gh,
                                         float iou, float cxa, float cya, float st,
                                         float b0s, float dco, bool valid, float c0) {
    const float R = 2.5f;
    bool in_box = (cxa > gx - 0.5f * gw) && (cxa < gx + 0.5f * gw) &&
                  (cya > gy - 0.5f * gh) && (cya < gy + 0.5f * gh);
    bool in_ctr = (cxa > gx - R * st) && (cxa < gx + R * st) &&
                  (cya > gy - R * st) && (cya < gy + R * st);
    bool in_both = in_box && in_ctr;
    float lt = (iou == 0.f) ? c0 : -logf(iou + 1e-8f);
    float cost = b0s + dco;
    cost += 3.0f * lt;
    cost += 100000.0f * (1.0f - (in_both ? 1.f : 0.f));
    // fg always true on compact list
    cost += valid ? 0.f : 1000000000.0f;
    return cost;
}

// ---------------- kernels ----------------
__global__ void k_init() {
    int i = blockIdx.x * blockDim.x + threadIdx.x;
    if (i < NB * NA) d_cnt[i] = 0;
    if (i < 4) d_acc[i] = 0.0;
    if (i < NA) {
        float st; int hw, W;
        if (i < A0)      { st = 8.f;  hw = i;      W = 80; }
        else if (i < A1) { st = 16.f; hw = i - A0; W = 40; }
        else             { st = 32.f; hw = i - A1; W = 20; }
        int x = hw % W, y = hw / W;
        d_geo[i] = make_float4((x + 0.5f) * st, (y + 0.5f) * st, st, 0.f);
    }
}

__global__ void k_decode(const float* __restrict__ f8,
                         const float* __restrict__ f16,
                         const float* __restrict__ f32_) {
    int i = blockIdx.x * blockDim.x + threadIdx.x;
    if (i >= NB * NA) return;
    int b = i / NA, a = i % NA;
    const float* f; int hw, HW, W; float st;
    if (a < A0)      { f = f8;   hw = a;      HW = 6400; W = 80; st = 8.f;  }
    else if (a < A1) { f = f16;  hw = a - A0; HW = 1600; W = 40; st = 16.f; }
    else             { f = f32_; hw = a - A1; HW = 400;  W = 20; st = 32.f; }
    float gx = (float)(hw % W), gy = (float)(hw / W);
    const float* base = f + (size_t)b * (5 + NC) * HW + hw;
    float tx = base[0 * HW], ty = base[(size_t)1 * HW];
    float tw = base[(size_t)2 * HW], th = base[(size_t)3 * HW];
    float to = base[(size_t)4 * HW];
    d_box[i] = make_float4((tx + gx) * st, (ty + gy) * st, expf(tw) * st, expf(th) * st);
    d_obj[i] = to;
}

// fg + per-chunk counts
__global__ void k_fg(const float* __restrict__ gtb, const int* __restrict__ ngts) {
    __shared__ float4 sgt[NG];
    int b = blockIdx.y;
    int n = ngts[b];
    if (threadIdx.x < NG) {
        const float* gb = gtb + ((size_t)b * NG + threadIdx.x) * 4;
        sgt[threadIdx.x] = make_float4(gb[0], gb[1], gb[2], gb[3]);
    }
    __syncthreads();
    int a = blockIdx.x * blockDim.x + threadIdx.x;
    bool fg = false;
    if (a < NA) {
        float4 ge = d_geo[a];
        float cxa = ge.x, cya = ge.y, st = ge.z;
        const float R = 2.5f;
        for (int g = 0; g < n; g++) {
            float4 gb = sgt[g];
            bool in_box = (cxa > gb.x - 0.5f * gb.z) && (cxa < gb.x + 0.5f * gb.z) &&
                          (cya > gb.y - 0.5f * gb.w) && (cya < gb.y + 0.5f * gb.w);
            bool in_ctr = (cxa > gb.x - R * st) && (cxa < gb.x + R * st) &&
                          (cya > gb.y - R * st) && (cya < gb.y + R * st);
            fg = fg || in_box || in_ctr;
        }
        d_fg[b * NA + a] = fg ? 1 : 0;
    }
    int c = __syncthreads_count(fg ? 1 : 0);
    if (threadIdx.x == 0) d_ccnt[b * NCH + blockIdx.x] = c;
}

// tiny per-image scan (32 threads, 33 values each)
__global__ void k_scan() {
    int b = threadIdx.x;
    if (b >= NB) return;
    int s = 0;
    for (int c = 0; c < NCH; c++) {
        d_coff[b * NCH + c] = s;
        s += d_ccnt[b * NCH + c];
    }
    d_fgcnt[b] = s;
}

// parallel scatter-compaction (grid 33 x 32)
__global__ void k_compact() {
    __shared__ int swcnt[8];
    __shared__ int swoff[8];
    int b = blockIdx.y, ch = blockIdx.x, tid = threadIdx.x;
    int warp = tid >> 5, lane = tid & 31;
    int a = ch * 256 + tid;
    bool flag = (a < NA) && d_fg[b * NA + a];
    unsigned bal = __ballot_sync(0xffffffffu, flag);
    int intra = __popc(bal & ((1u << lane) - 1u));
    if (lane == 0) swcnt[warp] = __popc(bal);
    __syncthreads();
    if (tid == 0) {
        int s = 0;
        for (int w = 0; w < 8; w++) { swoff[w] = s; s += swcnt[w]; }
    }
    __syncthreads();
    if (flag) {
        int j = d_coff[b * NCH + ch] + swoff[warp] + intra;
        d_fglist[b * NA + j] = a;
        d_fgpos[b * NA + a] = j;
        d_boxC[b * NA + j] = d_box[b * NA + a];
        d_geoC[b * NA + j] = d_geo[a];
    }
}

__global__ void k_clsprep(const float* __restrict__ f8, const float* __restrict__ f16,
                          const float* __restrict__ f32_) {
    int b = blockIdx.y;
    int j = blockIdx.x * blockDim.x + threadIdx.x;
    if (j >= d_fgcnt[b]) return;
    int a = d_fglist[b * NA + j];
    const float* f; int hw, HW;
    if (a < A0)      { f = f8;   hw = a;      HW = 6400; }
    else if (a < A1) { f = f16;  hw = a - A0; HW = 1600; }
    else             { f = f32_; hw = a - A1; HW = 400;  }
    const float* base = f + (size_t)b * (5 + NC) * HW + hw;
    float to = d_obj[b * NA + a];
    float so = 1.f / (1.f + expf(-to));
    float b0s = 0.f, sps = 0.f;
    for (int c = 0; c < NC; c++) {
        float x = base[(size_t)(5 + c) * HW];
        float sc = 1.f / (1.f + expf(-x));
        float p = sqrtf(sc * so);
        p = fminf(fmaxf(p, 1e-7f), 1.f - 1e-7f);
        float bce1 = -logf(p);
        float bce0 = -logf(1.f - p);
        b0s += bce0;
        d_dcoC[((size_t)b * NC + c) * NA + j] = bce1 - bce0;
        sps += fmaxf(x, 0.f) + log1pf(expf(-fabsf(x)));
    }
    d_b0sC[b * NA + j] = b0s;
    d_spsC[b * NA + j] = sps;
}

__global__ void k_assign(const float* __restrict__ gtb, const int* __restrict__ gtc,
                         const int* __restrict__ ngts) {
    int g = blockIdx.x, b = blockIdx.y, tid = threadIdx.x;
    if (g >= ngts[b]) return;

    __shared__ float s_lv[256 * TK];
    __shared__ int   s_li[256 * TK];
    __shared__ int   s_head[256];

    const float c0 = -logf(1e-8f);

    const float* gb = gtb + ((size_t)b * NG + g) * 4;
    float gx = gb[0], gy = gb[1], gw = gb[2], gh = gb[3];
    int gc = gtc[b * NG + g];
    int cnt = d_fgcnt[b];

    const float4* boxp = d_boxC + b * NA;
    const float4* geop = d_geoC + b * NA;
    const float* b0p = d_b0sC + b * NA;
    const float* dcop = d_dcoC + ((size_t)b * NC + gc) * NA;

    float iv[TK]; int ii[TK];
    float cv[TK]; int ci[TK];
#pragma unroll
    for (int k = 0; k < TK; k++) { iv[k] = -1.f; ii[k] = 0x7fffffff; cv[k] = 3.4e38f; ci[k] = 0x7fffffff; }

    for (int j = tid; j < cnt; j += 256) {
        float4 pb = boxp[j];
        float iou = iou_fn(gx, gy, gw, gh, pb);
        if (iou > iv[TK - 1] || (iou == iv[TK - 1] && j < ii[TK - 1])) {
            iv[TK - 1] = iou; ii[TK - 1] = j;
#pragma unroll
            for (int k = TK - 1; k > 0; k--) {
                if (iv[k] > iv[k - 1] || (iv[k] == iv[k - 1] && ii[k] < ii[k - 1])) {
                    float tv = iv[k]; iv[k] = iv[k - 1]; iv[k - 1] = tv;
                    int ti = ii[k]; ii[k] = ii[k - 1]; ii[k - 1] = ti;
                }
            }
        }
        float4 ge = geop[j];
        float cost = cost_fn(gx, gy, gw, gh, iou, ge.x, ge.y, ge.z, b0p[j], dcop[j], true, c0);
        if (cost < cv[TK - 1] || (cost == cv[TK - 1] && j < ci[TK - 1])) {
            cv[TK - 1] = cost; ci[TK - 1] = j;
#pragma unroll
            for (int k = TK - 1; k > 0; k--) {
                if (cv[k] < cv[k - 1] || (cv[k] == cv[k - 1] && ci[k] < ci[k - 1])) {
                    float tv = cv[k]; cv[k] = cv[k - 1]; cv[k - 1] = tv;
                    int ti = ci[k]; ci[k] = ci[k - 1]; ci[k - 1] = ti;
                }
            }
        }
    }

#pragma unroll
    for (int k = 0; k < TK; k++) { s_lv[tid * TK + k] = iv[k]; s_li[tid * TK + k] = ii[k]; }
    __syncthreads();
    if (tid < 32) {
        for (int l = tid; l < 256; l += 32) s_head[l] = 0;
        __syncwarp();
        float ksum = 0.f;
        for (int r = 0; r < TK; r++) {
            float bv = -2.f; int bi = 0x7fffffff; int bl = -1;
            for (int k = 0; k < 8; k++) {
                int l = tid + 32 * k;
                int hd = s_head[l];
                float v = s_lv[l * TK + hd]; int idx = s_li[l * TK + hd];
                if (v > bv || (v == bv && idx < bi)) { bv = v; bi = idx; bl = l; }
            }
            for (int o = 16; o; o >>= 1) {
                float ov = __shfl_xor_sync(0xffffffffu, bv, o);
                int oi = __shfl_xor_sync(0xffffffffu, bi, o);
                int ol = __shfl_xor_sync(0xffffffffu, bl, o);
                if (ov > bv || (ov == bv && oi < bi)) { bv = ov; bi = oi; bl = ol; }
            }
            ksum += fmaxf(bv, 0.f);
            if (tid == 0) s_head[bl]++;
            __syncwarp();
        }
        if (tid == 0) {
            int dk = (int)ksum;
            if (dk < 1) dk = 1;
            d_dynk[b * NG + g] = dk;
        }
    }
    __syncthreads();

#pragma unroll
    for (int k = 0; k < TK; k++) { s_lv[tid * TK + k] = cv[k]; s_li[tid * TK + k] = ci[k]; }
    __syncthreads();
    if (tid < 32) {
        for (int l = tid; l < 256; l += 32) s_head[l] = 0;
        __syncwarp();
        for (int r = 0; r < TK; r++) {
            float bv = 3.5e38f; int bi = 0x7fffffff; int bl = -1;
            for (int k = 0; k < 8; k++) {
                int l = tid + 32 * k;
                int hd = s_head[l];
                float v = s_lv[l * TK + hd]; int idx = s_li[l * TK + hd];
                if (v < bv || (v == bv && idx < bi)) { bv = v; bi = idx; bl = l; }
            }
            for (int o = 16; o; o >>= 1) {
                float ov = __shfl_xor_sync(0xffffffffu, bv, o);
                int oi = __shfl_xor_sync(0xffffffffu, bi, o);
                int ol = __shfl_xor_sync(0xffffffffu, bl, o);
                if (ov < bv || (ov == bv && oi < bi)) { bv = ov; bi = oi; bl = ol; }
            }
            if (tid == 0) {
                d_pos[(b * NG + g) * TK + r] = d_fglist[b * NA + bi];
                s_head[bl]++;
            }
            __syncwarp();
        }
    }
}

__global__ void k_scatter(const int* __restrict__ ngts) {
    int i = blockIdx.x * blockDim.x + threadIdx.x;
    if (i >= NB * NG) return;
    int b = i / NG, g = i % NG;
    if (g >= ngts[b]) return;
    int dk = d_dynk[i];
    for (int k = 0; k < dk; k++) {
        int a = d_pos[i * TK + k];
        atomicAdd(&d_cnt[b * NA + a], 1);
        d_lastg[b * NA + a] = g;
    }
}

__global__ void k_resolve(const float* __restrict__ gtb, const int* __restrict__ gtc,
                          const int* __restrict__ ngts) {
    int i = blockIdx.x * blockDim.x + threadIdx.x;
    if (i >= NB * NA) return;
    int b = i / NA, a = i % NA;
    int c = d_cnt[i];
    if (c == 0) { d_matched[i] = -1; d_prediou[i] = 0.f; return; }
    int mg;
    float4 pb = d_box[i];
    if (c == 1) {
        mg = d_lastg[i];
    } else {
        const float c0 = -logf(1e-8f);
        int n = ngts[b];
        int j = d_fgpos[i];
        float4 ge = d_geo[a];
        float b0s = d_b0sC[b * NA + j];
        float best = 3.5e38f; int bi = 0;
        for (int g = 0; g < NG; g++) {
            const float* gb = gtb + ((size_t)b * NG + g) * 4;
            float gx = gb[0], gy = gb[1], gw = gb[2], gh = gb[3];
            int gc = gtc[b * NG + g];
            float iou = iou_fn(gx, gy, gw, gh, pb);
            float dco = d_dcoC[((size_t)b * NC + gc) * NA + j];
            float cv = cost_fn(gx, gy, gw, gh, iou, ge.x, ge.y, ge.z, b0s, dco, g < n, c0);
            if (cv < best) { best = cv; bi = g; }
        }
        mg = bi;
    }
    d_matched[i] = mg;
    const float* gb = gtb + ((size_t)b * NG + mg) * 4;
    d_prediou[i] = iou_fn(gb[0], gb[1], gb[2], gb[3], pb);
}

__global__ void k_loss(const float* __restrict__ gtb, const int* __restrict__ gtc,
                       const float* __restrict__ f8, const float* __restrict__ f16,
                       const float* __restrict__ f32_) {
    __shared__ float s1[256], s2[256], s3[256];
    __shared__ int   s4[256];
    int tid = threadIdx.x;
    int i = blockIdx.x * blockDim.x + tid;
    float liou = 0.f, lobj = 0.f, lcls = 0.f; int nfg = 0;
    if (i < NB * NA) {
        int b = i / NA, a = i % NA;
        int mg = d_matched[i];
        bool fg = mg >= 0;
        float tgt = fg ? 0.9f : 0.f;
        float x = d_obj[i];
        lobj = fmaxf(x, 0.f) - x * tgt + log1pf(expf(-fabsf(x)));
        if (fg) {
            nfg = 1;
            const float* gb = gtb + ((size_t)b * NG + mg) * 4;
            float gx = gb[0], gy = gb[1], gw = gb[2], gh = gb[3];
            float4 pb = d_box[i];
            float tlx = fmaxf(pb.x - pb.z * 0.5f, gx - gw * 0.5f);
            float tly = fmaxf(pb.y - pb.w * 0.5f, gy - gh * 0.5f);
            float brx = fminf(pb.x + pb.z * 0.5f, gx + gw * 0.5f);
            float bry = fminf(pb.y + pb.w * 0.5f, gy + gh * 0.5f);
            bool en = (tlx < brx) && (tly < bry);
            float inter = en ? (brx - tlx) * (bry - tly) : 0.f;
            float uni = pb.z * pb.w + gw * gh - inter;
            float iou = inter / (uni + 1e-16f);
            liou = 1.f - iou * iou;
            int gc = gtc[b * NG + mg];
            const float* f; int hw, HW;
            if (a < A0)      { f = f8;   hw = a;      HW = 6400; }
            else if (a < A1) { f = f16;  hw = a - A0; HW = 1600; }
            else             { f = f32_; hw = a - A1; HW = 400;  }
            float cl = f[((size_t)b * (5 + NC) + 5 + gc) * HW + hw];
            lcls = d_spsC[b * NA + d_fgpos[i]] - cl * d_prediou[i];
        }
    }
    s1[tid] = liou; s2[tid] = lobj; s3[tid] = lcls; s4[tid] = nfg;
    __syncthreads();
    for (int s = 128; s > 0; s >>= 1) {
        if (tid < s) {
            s1[tid] += s1[tid + s]; s2[tid] += s2[tid + s];
            s3[tid] += s3[tid + s]; s4[tid] += s4[tid + s];
        }
        __syncthreads();
    }
    if (tid == 0) {
        atomicAdd(&d_acc[0], (double)s1[0]);
        atomicAdd(&d_acc[1], (double)s2[0]);
        atomicAdd(&d_acc[2], (double)s3[0]);
        atomicAdd(&d_acc[3], (double)s4[0]);
    }
}

__global__ void k_final(float* out) {
    double nfg = d_acc[3];
    if (nfg < 1.0) nfg = 1.0;
    out[0] = (float)((5.0 * d_acc[0] + d_acc[1] + d_acc[2]) / nfg);
}

// ---------------- launch ----------------
extern "C" void kernel_launch(void* const* d_in, const int* in_sizes, int n_in,
                              void* d_out, int out_size) {
    const float* f8   = (const float*)d_in[0];
    const float* f16  = (const float*)d_in[1];
    const float* f32_ = (const float*)d_in[2];
    const float* gtb  = (const float*)d_in[3];
    const int*   gtc  = (const int*)d_in[4];
    const int*   ngts = (const int*)d_in[5];
    float* out = (float*)d_out;

    const int NBA = NB * NA;
    const int T = 256;
    const int GBA = (NBA + T - 1) / T;

    k_init<<<GBA, T>>>();
    k_decode<<<GBA, T>>>(f8, f16, f32_);
    k_fg<<<dim3(NCH, NB), T>>>(gtb, ngts);
    k_scan<<<1, 32>>>();
    k_compact<<<dim3(NCH, NB), T>>>();
    k_clsprep<<<dim3(NCH, NB), T>>>(f8, f16, f32_);
    k_assign<<<dim3(NG, NB), T>>>(gtb, gtc, ngts);
    k_scatter<<<(NB * NG + T - 1) / T, T>>>(ngts);
    k_resolve<<<GBA, T>>>(gtb, gtc, ngts);
    k_loss<<<GBA, T>>>(gtb, gtc, f8, f16, f32_);
    k_final<<<1, 1>>>(out);
}

// round 6
// speedup vs baseline: 1.7510x; 1.0713x over previous
#include <cuda_runtime.h>
#include <cuda_bf16.h>
#include <math.h>

#define NB 32
#define NG 60
#define NC 80
#define NA 8400
#define A0 6400
#define A1 8000
#define TK 10
#define NCH 33   // ceil(NA/256)

// ---------------- device scratch ----------------
__device__ float4 d_box[NB * NA];
__device__ float  d_obj[NB * NA];
__device__ unsigned char d_fg[NB * NA];
__device__ float4 d_geo[NA];
__device__ int    d_ccnt[NB * NCH];
__device__ int    d_fglist[NB * NA];
__device__ int    d_fgpos[NB * NA];
__device__ int    d_fgcnt[NB];
__device__ float4 d_boxC[NB * NA];
__device__ float4 d_geoC[NB * NA];
__device__ float  d_b0sC[NB * NA];
__device__ float  d_spsC[NB * NA];
__device__ float  d_dcoC[(size_t)NB * NC * NA];
__device__ int    d_cnt[NB * NA];
__device__ int    d_lastg[NB * NA];
__device__ int    d_matched[NB * NA];
__device__ float  d_prediou[NB * NA];
__device__ double d_acc[4];

__device__ __forceinline__ float iou_fn(float gx, float gy, float gw, float gh, float4 pb) {
    float tlx = fmaxf(gx - gw * 0.5f, pb.x - pb.z * 0.5f);
    float tly = fmaxf(gy - gh * 0.5f, pb.y - pb.w * 0.5f);
    float brx = fminf(gx + gw * 0.5f, pb.x + pb.z * 0.5f);
    float bry = fminf(gy + gh * 0.5f, pb.y + pb.w * 0.5f);
    bool en = (tlx < brx) && (tly < bry);
    float inter = en ? (brx - tlx) * (bry - tly) : 0.f;
    return inter / (gw * gh + pb.z * pb.w - inter + 1e-16f);
}

__device__ __forceinline__ float cost_fn(float gx, float gy, float gw, float gh,
                                         float iou, float cxa, float cya, float st,
                                         float b0s, float dco, bool valid, float c0) {
    const float R = 2.5f;
    bool in_box = (cxa > gx - 0.5f * gw) && (cxa < gx + 0.5f * gw) &&
                  (cya > gy - 0.5f * gh) && (cya < gy + 0.5f * gh);
    bool in_ctr = (cxa > gx - R * st) && (cxa < gx + R * st) &&
                  (cya > gy - R * st) && (cya < gy + R * st);
    bool in_both = in_box && in_ctr;
    float lt = (iou == 0.f) ? c0 : -logf(iou + 1e-8f);
    float cost = b0s + dco;
    cost += 3.0f * lt;
    cost += 100000.0f * (1.0f - (in_both ? 1.f : 0.f));
    cost += valid ? 0.f : 1000000000.0f;
    return cost;
}

// ---------------- kernels ----------------
// decode + all init work folded in
__global__ void k_decode(const float* __restrict__ f8,
                         const float* __restrict__ f16,
                         const float* __restrict__ f32_) {
    int i = blockIdx.x * blockDim.x + threadIdx.x;
    if (i >= NB * NA) return;
    d_cnt[i] = 0;
    if (i < 4) d_acc[i] = 0.0;
    int b = i / NA, a = i % NA;
    const float* f; int hw, HW, W; float st;
    if (a < A0)      { f = f8;   hw = a;      HW = 6400; W = 80; st = 8.f;  }
    else if (a < A1) { f = f16;  hw = a - A0; HW = 1600; W = 40; st = 16.f; }
    else             { f = f32_; hw = a - A1; HW = 400;  W = 20; st = 32.f; }
    int xi = hw % W, yi = hw / W;
    float gx = (float)xi, gy = (float)yi;
    if (b == 0) d_geo[a] = make_float4((gx + 0.5f) * st, (gy + 0.5f) * st, st, 0.f);
    const float* base = f + (size_t)b * (5 + NC) * HW + hw;
    float tx = base[0 * HW], ty = base[(size_t)1 * HW];
    float tw = base[(size_t)2 * HW], th = base[(size_t)3 * HW];
    float to = base[(size_t)4 * HW];
    d_box[i] = make_float4((tx + gx) * st, (ty + gy) * st, expf(tw) * st, expf(th) * st);
    d_obj[i] = to;
}

__global__ void k_fg(const float* __restrict__ gtb, const int* __restrict__ ngts) {
    __shared__ float4 sgt[NG];
    int b = blockIdx.y;
    int n = ngts[b];
    if (threadIdx.x < NG) {
        const float* gb = gtb + ((size_t)b * NG + threadIdx.x) * 4;
        sgt[threadIdx.x] = make_float4(gb[0], gb[1], gb[2], gb[3]);
    }
    __syncthreads();
    int a = blockIdx.x * blockDim.x + threadIdx.x;
    bool fg = false;
    if (a < NA) {
        float4 ge = d_geo[a];
        float cxa = ge.x, cya = ge.y, st = ge.z;
        const float R = 2.5f;
        for (int g = 0; g < n; g++) {
            float4 gb = sgt[g];
            bool in_box = (cxa > gb.x - 0.5f * gb.z) && (cxa < gb.x + 0.5f * gb.z) &&
                          (cya > gb.y - 0.5f * gb.w) && (cya < gb.y + 0.5f * gb.w);
            bool in_ctr = (cxa > gb.x - R * st) && (cxa < gb.x + R * st) &&
                          (cya > gb.y - R * st) && (cya < gb.y + R * st);
            fg = fg || in_box || in_ctr;
        }
        d_fg[b * NA + a] = fg ? 1 : 0;
    }
    int c = __syncthreads_count(fg ? 1 : 0);
    if (threadIdx.x == 0) d_ccnt[b * NCH + blockIdx.x] = c;
}

// scatter-compaction with inline chunk-prefix (no separate scan kernel)
__global__ void k_compact() {
    __shared__ int swcnt[8];
    __shared__ int swoff[8];
    __shared__ int s_base;
    int b = blockIdx.y, ch = blockIdx.x, tid = threadIdx.x;
    int warp = tid >> 5, lane = tid & 31;
    // warp 0: prefix over earlier chunks (<=2 strided loads/lane)
    if (warp == 0) {
        int v = 0;
        for (int c = lane; c < ch; c += 32) v += d_ccnt[b * NCH + c];
        for (int o = 16; o; o >>= 1) v += __shfl_xor_sync(0xffffffffu, v, o);
        if (lane == 0) s_base = v;
    }
    int a = ch * 256 + tid;
    bool flag = (a < NA) && d_fg[b * NA + a];
    unsigned bal = __ballot_sync(0xffffffffu, flag);
    int intra = __popc(bal & ((1u << lane) - 1u));
    if (lane == 0) swcnt[warp] = __popc(bal);
    __syncthreads();
    if (tid == 0) {
        int s = 0;
        for (int w = 0; w < 8; w++) { swoff[w] = s; s += swcnt[w]; }
        if (ch == NCH - 1) d_fgcnt[b] = s_base + s;
    }
    __syncthreads();
    if (flag) {
        int j = s_base + swoff[warp] + intra;
        d_fglist[b * NA + j] = a;
        d_fgpos[b * NA + a] = j;
        d_boxC[b * NA + j] = d_box[b * NA + a];
        d_geoC[b * NA + j] = d_geo[a];
    }
}

__global__ void k_clsprep(const float* __restrict__ f8, const float* __restrict__ f16,
                          const float* __restrict__ f32_) {
    int b = blockIdx.y;
    int j = blockIdx.x * blockDim.x + threadIdx.x;
    if (j >= d_fgcnt[b]) return;
    int a = d_fglist[b * NA + j];
    const float* f; int hw, HW;
    if (a < A0)      { f = f8;   hw = a;      HW = 6400; }
    else if (a < A1) { f = f16;  hw = a - A0; HW = 1600; }
    else             { f = f32_; hw = a - A1; HW = 400;  }
    const float* base = f + (size_t)b * (5 + NC) * HW + hw;
    float to = d_obj[b * NA + a];
    float so = 1.f / (1.f + expf(-to));
    float b0s = 0.f, sps = 0.f;
    for (int c = 0; c < NC; c++) {
        float x = base[(size_t)(5 + c) * HW];
        float sc = 1.f / (1.f + expf(-x));
        float p = sqrtf(sc * so);
        p = fminf(fmaxf(p, 1e-7f), 1.f - 1e-7f);
        float bce1 = -logf(p);
        float bce0 = -logf(1.f - p);
        b0s += bce0;
        d_dcoC[((size_t)b * NC + c) * NA + j] = bce1 - bce0;
        sps += fmaxf(x, 0.f) + log1pf(expf(-fabsf(x)));
    }
    d_b0sC[b * NA + j] = b0s;
    d_spsC[b * NA + j] = sps;
}

// fused cost+iou + top-k + inline scatter
__global__ void k_assign(const float* __restrict__ gtb, const int* __restrict__ gtc,
                         const int* __restrict__ ngts) {
    int g = blockIdx.x, b = blockIdx.y, tid = threadIdx.x;
    if (g >= ngts[b]) return;

    __shared__ float s_lv[256 * TK];
    __shared__ int   s_li[256 * TK];
    __shared__ int   s_head[256];

    const float c0 = -logf(1e-8f);

    const float* gb = gtb + ((size_t)b * NG + g) * 4;
    float gx = gb[0], gy = gb[1], gw = gb[2], gh = gb[3];
    int gc = gtc[b * NG + g];
    int cnt = d_fgcnt[b];

    const float4* boxp = d_boxC + b * NA;
    const float4* geop = d_geoC + b * NA;
    const float* b0p = d_b0sC + b * NA;
    const float* dcop = d_dcoC + ((size_t)b * NC + gc) * NA;

    float iv[TK]; int ii[TK];
    float cv[TK]; int ci[TK];
#pragma unroll
    for (int k = 0; k < TK; k++) { iv[k] = -1.f; ii[k] = 0x7fffffff; cv[k] = 3.4e38f; ci[k] = 0x7fffffff; }

    for (int j = tid; j < cnt; j += 256) {
        float4 pb = boxp[j];
        float iou = iou_fn(gx, gy, gw, gh, pb);
        if (iou > iv[TK - 1] || (iou == iv[TK - 1] && j < ii[TK - 1])) {
            iv[TK - 1] = iou; ii[TK - 1] = j;
#pragma unroll
            for (int k = TK - 1; k > 0; k--) {
                if (iv[k] > iv[k - 1] || (iv[k] == iv[k - 1] && ii[k] < ii[k - 1])) {
                    float tv = iv[k]; iv[k] = iv[k - 1]; iv[k - 1] = tv;
                    int ti = ii[k]; ii[k] = ii[k - 1]; ii[k - 1] = ti;
                }
            }
        }
        float4 ge = geop[j];
        float cost = cost_fn(gx, gy, gw, gh, iou, ge.x, ge.y, ge.z, b0p[j], dcop[j], true, c0);
        if (cost < cv[TK - 1] || (cost == cv[TK - 1] && j < ci[TK - 1])) {
            cv[TK - 1] = cost; ci[TK - 1] = j;
#pragma unroll
            for (int k = TK - 1; k > 0; k--) {
                if (cv[k] < cv[k - 1] || (cv[k] == cv[k - 1] && ci[k] < ci[k - 1])) {
                    float tv = cv[k]; cv[k] = cv[k - 1]; cv[k - 1] = tv;
                    int ti = ci[k]; ci[k] = ci[k - 1]; ci[k - 1] = ti;
                }
            }
        }
    }

    int dk_local = 1;

#pragma unroll
    for (int k = 0; k < TK; k++) { s_lv[tid * TK + k] = iv[k]; s_li[tid * TK + k] = ii[k]; }
    __syncthreads();
    if (tid < 32) {
        for (int l = tid; l < 256; l += 32) s_head[l] = 0;
        __syncwarp();
        float ksum = 0.f;
        for (int r = 0; r < TK; r++) {
            float bv = -2.f; int bi = 0x7fffffff; int bl = -1;
            for (int k = 0; k < 8; k++) {
                int l = tid + 32 * k;
                int hd = s_head[l];
                float v = s_lv[l * TK + hd]; int idx = s_li[l * TK + hd];
                if (v > bv || (v == bv && idx < bi)) { bv = v; bi = idx; bl = l; }
            }
            for (int o = 16; o; o >>= 1) {
                float ov = __shfl_xor_sync(0xffffffffu, bv, o);
                int oi = __shfl_xor_sync(0xffffffffu, bi, o);
                int ol = __shfl_xor_sync(0xffffffffu, bl, o);
                if (ov > bv || (ov == bv && oi < bi)) { bv = ov; bi = oi; bl = ol; }
            }
            ksum += fmaxf(bv, 0.f);
            if (tid == 0) s_head[bl]++;
            __syncwarp();
        }
        if (tid == 0) {
            dk_local = (int)ksum;
            if (dk_local < 1) dk_local = 1;
        }
    }
    __syncthreads();

#pragma unroll
    for (int k = 0; k < TK; k++) { s_lv[tid * TK + k] = cv[k]; s_li[tid * TK + k] = ci[k]; }
    __syncthreads();
    if (tid < 32) {
        for (int l = tid; l < 256; l += 32) s_head[l] = 0;
        __syncwarp();
        int pa[TK];
        for (int r = 0; r < TK; r++) {
            float bv = 3.5e38f; int bi = 0x7fffffff; int bl = -1;
            for (int k = 0; k < 8; k++) {
                int l = tid + 32 * k;
                int hd = s_head[l];
                float v = s_lv[l * TK + hd]; int idx = s_li[l * TK + hd];
                if (v < bv || (v == bv && idx < bi)) { bv = v; bi = idx; bl = l; }
            }
            for (int o = 16; o; o >>= 1) {
                float ov = __shfl_xor_sync(0xffffffffu, bv, o);
                int oi = __shfl_xor_sync(0xffffffffu, bi, o);
                int ol = __shfl_xor_sync(0xffffffffu, bl, o);
                if (ov < bv || (ov == bv && oi < bi)) { bv = ov; bi = oi; bl = ol; }
            }
            if (tid == 0) {
                pa[r] = bi;
                s_head[bl]++;
            }
            __syncwarp();
        }
        // inline scatter: matching[g, pos[0..dk)] = 1
        if (tid == 0) {
            for (int r = 0; r < dk_local; r++) {
                int a = d_fglist[b * NA + pa[r]];
                atomicAdd(&d_cnt[b * NA + a], 1);
                d_lastg[b * NA + a] = g;
            }
        }
    }
}

__global__ void k_resolve(const float* __restrict__ gtb, const int* __restrict__ gtc,
                          const int* __restrict__ ngts) {
    int i = blockIdx.x * blockDim.x + threadIdx.x;
    if (i >= NB * NA) return;
    int c = d_cnt[i];
    if (c == 0) { d_matched[i] = -1; d_prediou[i] = 0.f; return; }
    int b = i / NA, a = i % NA;
    float4 pb = d_box[i];
    int mg;
    if (c == 1) {
        mg = d_lastg[i];
    } else {
        const float c0 = -logf(1e-8f);
        int n = ngts[b];
        int j = d_fgpos[i];
        float4 ge = d_geo[a];
        float b0s = d_b0sC[b * NA + j];
        float best = 3.5e38f; int bi = 0;
        for (int g = 0; g < NG; g++) {
            const float* gb = gtb + ((size_t)b * NG + g) * 4;
            float gx = gb[0], gy = gb[1], gw = gb[2], gh = gb[3];
            int gc = gtc[b * NG + g];
            float iou = iou_fn(gx, gy, gw, gh, pb);
            float dco = d_dcoC[((size_t)b * NC + gc) * NA + j];
            float cv = cost_fn(gx, gy, gw, gh, iou, ge.x, ge.y, ge.z, b0s, dco, g < n, c0);
            if (cv < best) { best = cv; bi = g; }
        }
        mg = bi;
    }
    d_matched[i] = mg;
    const float* gb = gtb + ((size_t)b * NG + mg) * 4;
    d_prediou[i] = iou_fn(gb[0], gb[1], gb[2], gb[3], pb);
}

__global__ void k_loss(const float* __restrict__ gtb, const int* __restrict__ gtc,
                       const float* __restrict__ f8, const float* __restrict__ f16,
                       const float* __restrict__ f32_) {
    __shared__ float s1[256], s2[256], s3[256];
    __shared__ int   s4[256];
    int tid = threadIdx.x;
    int i = blockIdx.x * blockDim.x + tid;
    float liou = 0.f, lobj = 0.f, lcls = 0.f; int nfg = 0;
    if (i < NB * NA) {
        int b = i / NA, a = i % NA;
        int mg = d_matched[i];
        bool fg = mg >= 0;
        float tgt = fg ? 0.9f : 0.f;
        float x = d_obj[i];
        lobj = fmaxf(x, 0.f) - x * tgt + log1pf(expf(-fabsf(x)));
        if (fg) {
            nfg = 1;
            const float* gb = gtb + ((size_t)b * NG + mg) * 4;
            float gx = gb[0], gy = gb[1], gw = gb[2], gh = gb[3];
            float4 pb = d_box[i];
            float tlx = fmaxf(pb.x - pb.z * 0.5f, gx - gw * 0.5f);
            float tly = fmaxf(pb.y - pb.w * 0.5f, gy - gh * 0.5f);
            float brx = fminf(pb.x + pb.z * 0.5f, gx + gw * 0.5f);
            float bry = fminf(pb.y + pb.w * 0.5f, gy + gh * 0.5f);
            bool en = (tlx < brx) && (tly < bry);
            float inter = en ? (brx - tlx) * (bry - tly) : 0.f;
            float uni = pb.z * pb.w + gw * gh - inter;
            float iou = inter / (uni + 1e-16f);
            liou = 1.f - iou * iou;
            int gc = gtc[b * NG + mg];
            const float* f; int hw, HW;
            if (a < A0)      { f = f8;   hw = a;      HW = 6400; }
            else if (a < A1) { f = f16;  hw = a - A0; HW = 1600; }
            else             { f = f32_; hw = a - A1; HW = 400;  }
            float cl = f[((size_t)b * (5 + NC) + 5 + gc) * HW + hw];
            lcls = d_spsC[b * NA + d_fgpos[i]] - cl * d_prediou[i];
        }
    }
    s1[tid] = liou; s2[tid] = lobj; s3[tid] = lcls; s4[tid] = nfg;
    __syncthreads();
    for (int s = 128; s > 0; s >>= 1) {
        if (tid < s) {
            s1[tid] += s1[tid + s]; s2[tid] += s2[tid + s];
            s3[tid] += s3[tid + s]; s4[tid] += s4[tid + s];
        }
        __syncthreads();
    }
    if (tid == 0) {
        atomicAdd(&d_acc[0], (double)s1[0]);
        atomicAdd(&d_acc[1], (double)s2[0]);
        atomicAdd(&d_acc[2], (double)s3[0]);
        atomicAdd(&d_acc[3], (double)s4[0]);
    }
}

__global__ void k_final(float* out) {
    double nfg = d_acc[3];
    if (nfg < 1.0) nfg = 1.0;
    out[0] = (float)((5.0 * d_acc[0] + d_acc[1] + d_acc[2]) / nfg);
}

// ---------------- launch ----------------
extern "C" void kernel_launch(void* const* d_in, const int* in_sizes, int n_in,
                              void* d_out, int out_size) {
    const float* f8   = (const float*)d_in[0];
    const float* f16  = (const float*)d_in[1];
    const float* f32_ = (const float*)d_in[2];
    const float* gtb  = (const float*)d_in[3];
    const int*   gtc  = (const int*)d_in[4];
    const int*   ngts = (const int*)d_in[5];
    float* out = (float*)d_out;

    const int NBA = NB * NA;
    const int T = 256;
    const int GBA = (NBA + T - 1) / T;

    k_decode<<<GBA, T>>>(f8, f16, f32_);
    k_fg<<<dim3(NCH, NB), T>>>(gtb, ngts);
    k_compact<<<dim3(NCH, NB), T>>>();
    k_clsprep<<<dim3(NCH, NB), T>>>(f8, f16, f32_);
    k_assign<<<dim3(NG, NB), T>>>(gtb, gtc, ngts);
    k_resolve<<<GBA, T>>>(gtb, gtc, ngts);
    k_loss<<<GBA, T>>>(gtb, gtc, f8, f16, f32_);
    k_final<<<1, 1>>>(out);
}

// round 7
// speedup vs baseline: 2.0061x; 1.1457x over previous
#include <cuda_runtime.h>
#include <cuda_bf16.h>
#include <math.h>

#define NB 32
#define NG 60
#define NC 80
#define NA 8400
#define A0 6400
#define A1 8000
#define TK 10
#define NCH 33   // ceil(NA/256)
#define NCH64 132 // ceil(NA/64)

// ---------------- device scratch ----------------
__device__ float4 d_box[NB * NA];
__device__ float  d_obj[NB * NA];
__device__ unsigned char d_fg[NB * NA];
__device__ float4 d_geo[NA];
__device__ int    d_ccnt[NB * NCH];
__device__ int    d_fglist[NB * NA];
__device__ int    d_fgpos[NB * NA];
__device__ int    d_fgcnt[NB];
__device__ float4 d_boxC[NB * NA];
__device__ float4 d_geoC[NB * NA];
__device__ float  d_b0sC[NB * NA];
__device__ float  d_spsC[NB * NA];
__device__ float  d_dcoC[(size_t)NB * NC * NA];
__device__ int    d_cnt[NB * NA];
__device__ int    d_lastg[NB * NA];
__device__ int    d_matched[NB * NA];
__device__ float  d_prediou[NB * NA];
__device__ double d_acc[4];

__device__ __forceinline__ float iou_fn(float gx, float gy, float gw, float gh, float4 pb) {
    float tlx = fmaxf(gx - gw * 0.5f, pb.x - pb.z * 0.5f);
    float tly = fmaxf(gy - gh * 0.5f, pb.y - pb.w * 0.5f);
    float brx = fminf(gx + gw * 0.5f, pb.x + pb.z * 0.5f);
    float bry = fminf(gy + gh * 0.5f, pb.y + pb.w * 0.5f);
    bool en = (tlx < brx) && (tly < bry);
    float inter = en ? (brx - tlx) * (bry - tly) : 0.f;
    return inter / (gw * gh + pb.z * pb.w - inter + 1e-16f);
}

__device__ __forceinline__ float cost_fn(float gx, float gy, float gw, float gh,
                                         float iou, float cxa, float cya, float st,
                                         float b0s, float dco, bool valid, float c0) {
    const float R = 2.5f;
    bool in_box = (cxa > gx - 0.5f * gw) && (cxa < gx + 0.5f * gw) &&
                  (cya > gy - 0.5f * gh) && (cya < gy + 0.5f * gh);
    bool in_ctr = (cxa > gx - R * st) && (cxa < gx + R * st) &&
                  (cya > gy - R * st) && (cya < gy + R * st);
    bool in_both = in_box && in_ctr;
    float lt = (iou == 0.f) ? c0 : -logf(iou + 1e-8f);
    float cost = b0s + dco;
    cost += 3.0f * lt;
    cost += 100000.0f * (1.0f - (in_both ? 1.f : 0.f));
    cost += valid ? 0.f : 1000000000.0f;
    return cost;
}

// ---------------- kernels ----------------
__global__ void k_decode(const float* __restrict__ f8,
                         const float* __restrict__ f16,
                         const float* __restrict__ f32_) {
    int i = blockIdx.x * blockDim.x + threadIdx.x;
    if (i >= NB * NA) return;
    d_cnt[i] = 0;
    if (i < 4) d_acc[i] = 0.0;
    int b = i / NA, a = i % NA;
    const float* f; int hw, HW, W; float st;
    if (a < A0)      { f = f8;   hw = a;      HW = 6400; W = 80; st = 8.f;  }
    else if (a < A1) { f = f16;  hw = a - A0; HW = 1600; W = 40; st = 16.f; }
    else             { f = f32_; hw = a - A1; HW = 400;  W = 20; st = 32.f; }
    int xi = hw % W, yi = hw / W;
    float gx = (float)xi, gy = (float)yi;
    if (b == 0) d_geo[a] = make_float4((gx + 0.5f) * st, (gy + 0.5f) * st, st, 0.f);
    const float* base = f + (size_t)b * (5 + NC) * HW + hw;
    float tx = base[0 * HW], ty = base[(size_t)1 * HW];
    float tw = base[(size_t)2 * HW], th = base[(size_t)3 * HW];
    float to = base[(size_t)4 * HW];
    d_box[i] = make_float4((tx + gx) * st, (ty + gy) * st, expf(tw) * st, expf(th) * st);
    d_obj[i] = to;
}

__global__ void k_fg(const float* __restrict__ gtb, const int* __restrict__ ngts) {
    __shared__ float4 sgt[NG];
    int b = blockIdx.y;
    int n = ngts[b];
    if (threadIdx.x < NG) {
        const float* gb = gtb + ((size_t)b * NG + threadIdx.x) * 4;
        sgt[threadIdx.x] = make_float4(gb[0], gb[1], gb[2], gb[3]);
    }
    __syncthreads();
    int a = blockIdx.x * blockDim.x + threadIdx.x;
    bool fg = false;
    if (a < NA) {
        float4 ge = d_geo[a];
        float cxa = ge.x, cya = ge.y, st = ge.z;
        const float R = 2.5f;
        for (int g = 0; g < n; g++) {
            float4 gb = sgt[g];
            bool in_box = (cxa > gb.x - 0.5f * gb.z) && (cxa < gb.x + 0.5f * gb.z) &&
                          (cya > gb.y - 0.5f * gb.w) && (cya < gb.y + 0.5f * gb.w);
            bool in_ctr = (cxa > gb.x - R * st) && (cxa < gb.x + R * st) &&
                          (cya > gb.y - R * st) && (cya < gb.y + R * st);
            fg = fg || in_box || in_ctr;
        }
        d_fg[b * NA + a] = fg ? 1 : 0;
    }
    int c = __syncthreads_count(fg ? 1 : 0);
    if (threadIdx.x == 0) d_ccnt[b * NCH + blockIdx.x] = c;
}

__global__ void k_compact() {
    __shared__ int swcnt[8];
    __shared__ int swoff[8];
    __shared__ int s_base;
    int b = blockIdx.y, ch = blockIdx.x, tid = threadIdx.x;
    int warp = tid >> 5, lane = tid & 31;
    if (warp == 0) {
        int v = 0;
        for (int c = lane; c < ch; c += 32) v += d_ccnt[b * NCH + c];
        for (int o = 16; o; o >>= 1) v += __shfl_xor_sync(0xffffffffu, v, o);
        if (lane == 0) s_base = v;
    }
    int a = ch * 256 + tid;
    bool flag = (a < NA) && d_fg[b * NA + a];
    unsigned bal = __ballot_sync(0xffffffffu, flag);
    int intra = __popc(bal & ((1u << lane) - 1u));
    if (lane == 0) swcnt[warp] = __popc(bal);
    __syncthreads();
    if (tid == 0) {
        int s = 0;
        for (int w = 0; w < 8; w++) { swoff[w] = s; s += swcnt[w]; }
        if (ch == NCH - 1) d_fgcnt[b] = s_base + s;
    }
    __syncthreads();
    if (flag) {
        int j = s_base + swoff[warp] + intra;
        d_fglist[b * NA + j] = a;
        d_fgpos[b * NA + a] = j;
        d_boxC[b * NA + j] = d_box[b * NA + a];
        d_geoC[b * NA + j] = d_geo[a];
    }
}

// class BCE precompute: 64 anchors x 4 class-groups per block (4x parallelism)
__global__ void k_clsprep(const float* __restrict__ f8, const float* __restrict__ f16,
                          const float* __restrict__ f32_) {
    __shared__ float s_b0[256];
    __shared__ float s_sp[256];
    int b = blockIdx.y;
    int tid = threadIdx.x;
    int jl = tid & 63;          // anchor within block
    int grp = tid >> 6;         // class group 0..3
    int j = blockIdx.x * 64 + jl;
    int cnt = d_fgcnt[b];
    float b0s = 0.f, sps = 0.f;
    if (j < cnt) {
        int a = d_fglist[b * NA + j];
        const float* f; int hw, HW;
        if (a < A0)      { f = f8;   hw = a;      HW = 6400; }
        else if (a < A1) { f = f16;  hw = a - A0; HW = 1600; }
        else             { f = f32_; hw = a - A1; HW = 400;  }
        const float* base = f + (size_t)b * (5 + NC) * HW + hw;
        float to = d_obj[b * NA + a];
        float so = 1.f / (1.f + expf(-to));
        int c0i = grp * 20;
#pragma unroll 5
        for (int c = c0i; c < c0i + 20; c++) {
            float x = base[(size_t)(5 + c) * HW];
            float sc = 1.f / (1.f + expf(-x));
            float p = sqrtf(sc * so);
            p = fminf(fmaxf(p, 1e-7f), 1.f - 1e-7f);
            float bce1 = -logf(p);
            float bce0 = -logf(1.f - p);
            b0s += bce0;
            d_dcoC[((size_t)b * NC + c) * NA + j] = bce1 - bce0;
            sps += fmaxf(x, 0.f) + log1pf(expf(-fabsf(x)));
        }
    }
    s_b0[tid] = b0s;
    s_sp[tid] = sps;
    __syncthreads();
    if (grp == 0 && j < cnt) {
        float tb = (s_b0[jl] + s_b0[64 + jl]) + (s_b0[128 + jl] + s_b0[192 + jl]);
        float ts = (s_sp[jl] + s_sp[64 + jl]) + (s_sp[128 + jl] + s_sp[192 + jl]);
        d_b0sC[b * NA + j] = tb;
        d_spsC[b * NA + j] = ts;
    }
}

// fused cost+iou + top-k + inline scatter
__global__ void k_assign(const float* __restrict__ gtb, const int* __restrict__ gtc,
                         const int* __restrict__ ngts) {
    int g = blockIdx.x, b = blockIdx.y, tid = threadIdx.x;
    if (g >= ngts[b]) return;

    __shared__ float s_lv[256 * TK];
    __shared__ int   s_li[256 * TK];
    __shared__ int   s_head[256];

    const float c0 = -logf(1e-8f);

    const float* gb = gtb + ((size_t)b * NG + g) * 4;
    float gx = gb[0], gy = gb[1], gw = gb[2], gh = gb[3];
    int gc = gtc[b * NG + g];
    int cnt = d_fgcnt[b];

    const float4* boxp = d_boxC + b * NA;
    const float4* geop = d_geoC + b * NA;
    const float* b0p = d_b0sC + b * NA;
    const float* dcop = d_dcoC + ((size_t)b * NC + gc) * NA;

    float iv[TK]; int ii[TK];
    float cv[TK]; int ci[TK];
#pragma unroll
    for (int k = 0; k < TK; k++) { iv[k] = -1.f; ii[k] = 0x7fffffff; cv[k] = 3.4e38f; ci[k] = 0x7fffffff; }

    for (int j = tid; j < cnt; j += 256) {
        float4 pb = boxp[j];
        float iou = iou_fn(gx, gy, gw, gh, pb);
        if (iou > iv[TK - 1] || (iou == iv[TK - 1] && j < ii[TK - 1])) {
            iv[TK - 1] = iou; ii[TK - 1] = j;
#pragma unroll
            for (int k = TK - 1; k > 0; k--) {
                if (iv[k] > iv[k - 1] || (iv[k] == iv[k - 1] && ii[k] < ii[k - 1])) {
                    float tv = iv[k]; iv[k] = iv[k - 1]; iv[k - 1] = tv;
                    int ti = ii[k]; ii[k] = ii[k - 1]; ii[k - 1] = ti;
                }
            }
        }
        float4 ge = geop[j];
        float cost = cost_fn(gx, gy, gw, gh, iou, ge.x, ge.y, ge.z, b0p[j], dcop[j], true, c0);
        if (cost < cv[TK - 1] || (cost == cv[TK - 1] && j < ci[TK - 1])) {
            cv[TK - 1] = cost; ci[TK - 1] = j;
#pragma unroll
            for (int k = TK - 1; k > 0; k--) {
                if (cv[k] < cv[k - 1] || (cv[k] == cv[k - 1] && ci[k] < ci[k - 1])) {
                    float tv = cv[k]; cv[k] = cv[k - 1]; cv[k - 1] = tv;
                    int ti = ci[k]; ci[k] = ci[k - 1]; ci[k - 1] = ti;
                }
            }
        }
    }

    int dk_local = 1;

#pragma unroll
    for (int k = 0; k < TK; k++) { s_lv[tid * TK + k] = iv[k]; s_li[tid * TK + k] = ii[k]; }
    __syncthreads();
    if (tid < 32) {
        for (int l = tid; l < 256; l += 32) s_head[l] = 0;
        __syncwarp();
        float ksum = 0.f;
        for (int r = 0; r < TK; r++) {
            float bv = -2.f; int bi = 0x7fffffff; int bl = -1;
            for (int k = 0; k < 8; k++) {
                int l = tid + 32 * k;
                int hd = s_head[l];
                float v = s_lv[l * TK + hd]; int idx = s_li[l * TK + hd];
                if (v > bv || (v == bv && idx < bi)) { bv = v; bi = idx; bl = l; }
            }
            for (int o = 16; o; o >>= 1) {
                float ov = __shfl_xor_sync(0xffffffffu, bv, o);
                int oi = __shfl_xor_sync(0xffffffffu, bi, o);
                int ol = __shfl_xor_sync(0xffffffffu, bl, o);
                if (ov > bv || (ov == bv && oi < bi)) { bv = ov; bi = oi; bl = ol; }
            }
            ksum += fmaxf(bv, 0.f);
            if (tid == 0) s_head[bl]++;
            __syncwarp();
        }
        if (tid == 0) {
            dk_local = (int)ksum;
            if (dk_local < 1) dk_local = 1;
        }
    }
    __syncthreads();

#pragma unroll
    for (int k = 0; k < TK; k++) { s_lv[tid * TK + k] = cv[k]; s_li[tid * TK + k] = ci[k]; }
    __syncthreads();
    if (tid < 32) {
        for (int l = tid; l < 256; l += 32) s_head[l] = 0;
        __syncwarp();
        int pa[TK];
        for (int r = 0; r < TK; r++) {
            float bv = 3.5e38f; int bi = 0x7fffffff; int bl = -1;
            for (int k = 0; k < 8; k++) {
                int l = tid + 32 * k;
                int hd = s_head[l];
                float v = s_lv[l * TK + hd]; int idx = s_li[l * TK + hd];
                if (v < bv || (v == bv && idx < bi)) { bv = v; bi = idx; bl = l; }
            }
            for (int o = 16; o; o >>= 1) {
                float ov = __shfl_xor_sync(0xffffffffu, bv, o);
                int oi = __shfl_xor_sync(0xffffffffu, bi, o);
                int ol = __shfl_xor_sync(0xffffffffu, bl, o);
                if (ov < bv || (ov == bv && oi < bi)) { bv = ov; bi = oi; bl = ol; }
            }
            if (tid == 0) {
                pa[r] = bi;
                s_head[bl]++;
            }
            __syncwarp();
        }
        if (tid == 0) {
            for (int r = 0; r < dk_local; r++) {
                int a = d_fglist[b * NA + pa[r]];
                atomicAdd(&d_cnt[b * NA + a], 1);
                d_lastg[b * NA + a] = g;
            }
        }
    }
}

__global__ void k_resolve(const float* __restrict__ gtb, const int* __restrict__ gtc,
                          const int* __restrict__ ngts) {
    int i = blockIdx.x * blockDim.x + threadIdx.x;
    if (i >= NB * NA) return;
    int c = d_cnt[i];
    if (c == 0) { d_matched[i] = -1; d_prediou[i] = 0.f; return; }
    int b = i / NA, a = i % NA;
    float4 pb = d_box[i];
    int mg;
    if (c == 1) {
        mg = d_lastg[i];
    } else {
        const float c0 = -logf(1e-8f);
        int n = ngts[b];
        int j = d_fgpos[i];
        float4 ge = d_geo[a];
        float b0s = d_b0sC[b * NA + j];
        float best = 3.5e38f; int bi = 0;
        for (int g = 0; g < NG; g++) {
            const float* gb = gtb + ((size_t)b * NG + g) * 4;
            float gx = gb[0], gy = gb[1], gw = gb[2], gh = gb[3];
            int gc = gtc[b * NG + g];
            float iou = iou_fn(gx, gy, gw, gh, pb);
            float dco = d_dcoC[((size_t)b * NC + gc) * NA + j];
            float cv = cost_fn(gx, gy, gw, gh, iou, ge.x, ge.y, ge.z, b0s, dco, g < n, c0);
            if (cv < best) { best = cv; bi = g; }
        }
        mg = bi;
    }
    d_matched[i] = mg;
    const float* gb = gtb + ((size_t)b * NG + mg) * 4;
    d_prediou[i] = iou_fn(gb[0], gb[1], gb[2], gb[3], pb);
}

__global__ void k_loss(const float* __restrict__ gtb, const int* __restrict__ gtc,
                       const float* __restrict__ f8, const float* __restrict__ f16,
                       const float* __restrict__ f32_) {
    __shared__ float s1[256], s2[256], s3[256];
    __shared__ int   s4[256];
    int tid = threadIdx.x;
    int i = blockIdx.x * blockDim.x + tid;
    float liou = 0.f, lobj = 0.f, lcls = 0.f; int nfg = 0;
    if (i < NB * NA) {
        int b = i / NA, a = i % NA;
        int mg = d_matched[i];
        bool fg = mg >= 0;
        float tgt = fg ? 0.9f : 0.f;
        float x = d_obj[i];
        lobj = fmaxf(x, 0.f) - x * tgt + log1pf(expf(-fabsf(x)));
        if (fg) {
            nfg = 1;
            const float* gb = gtb + ((size_t)b * NG + mg) * 4;
            float gx = gb[0], gy = gb[1], gw = gb[2], gh = gb[3];
            float4 pb = d_box[i];
            float tlx = fmaxf(pb.x - pb.z * 0.5f, gx - gw * 0.5f);
            float tly = fmaxf(pb.y - pb.w * 0.5f, gy - gh * 0.5f);
            float brx = fminf(pb.x + pb.z * 0.5f, gx + gw * 0.5f);
            float bry = fminf(pb.y + pb.w * 0.5f, gy + gh * 0.5f);
            bool en = (tlx < brx) && (tly < bry);
            float inter = en ? (brx - tlx) * (bry - tly) : 0.f;
            float uni = pb.z * pb.w + gw * gh - inter;
            float iou = inter / (uni + 1e-16f);
            liou = 1.f - iou * iou;
            int gc = gtc[b * NG + mg];
            const float* f; int hw, HW;
            if (a < A0)      { f = f8;   hw = a;      HW = 6400; }
            else if (a < A1) { f = f16;  hw = a - A0; HW = 1600; }
            else             { f = f32_; hw = a - A1; HW = 400;  }
            float cl = f[((size_t)b * (5 + NC) + 5 + gc) * HW + hw];
            lcls = d_spsC[b * NA + d_fgpos[i]] - cl * d_prediou[i];
        }
    }
    s1[tid] = liou; s2[tid] = lobj; s3[tid] = lcls; s4[tid] = nfg;
    __syncthreads();
    for (int s = 128; s > 0; s >>= 1) {
        if (tid < s) {
            s1[tid] += s1[tid + s]; s2[tid] += s2[tid + s];
            s3[tid] += s3[tid + s]; s4[tid] += s4[tid + s];
        }
        __syncthreads();
    }
    if (tid == 0) {
        atomicAdd(&d_acc[0], (double)s1[0]);
        atomicAdd(&d_acc[1], (double)s2[0]);
        atomicAdd(&d_acc[2], (double)s3[0]);
        atomicAdd(&d_acc[3], (double)s4[0]);
    }
}

__global__ void k_final(float* out) {
    double nfg = d_acc[3];
    if (nfg < 1.0) nfg = 1.0;
    out[0] = (float)((5.0 * d_acc[0] + d_acc[1] + d_acc[2]) / nfg);
}

// ---------------- launch ----------------
extern "C" void kernel_launch(void* const* d_in, const int* in_sizes, int n_in,
                              void* d_out, int out_size) {
    const float* f8   = (const float*)d_in[0];
    const float* f16  = (const float*)d_in[1];
    const float* f32_ = (const float*)d_in[2];
    const float* gtb  = (const float*)d_in[3];
    const int*   gtc  = (const int*)d_in[4];
    const int*   ngts = (const int*)d_in[5];
    float* out = (float*)d_out;

    const int NBA = NB * NA;
    const int T = 256;
    const int GBA = (NBA + T - 1) / T;

    k_decode<<<GBA, T>>>(f8, f16, f32_);
    k_fg<<<dim3(NCH, NB), T>>>(gtb, ngts);
    k_compact<<<dim3(NCH, NB), T>>>();
    k_clsprep<<<dim3(NCH64, NB), T>>>(f8, f16, f32_);
    k_assign<<<dim3(NG, NB), T>>>(gtb, gtc, ngts);
    k_resolve<<<GBA, T>>>(gtb, gtc, ngts);
    k_loss<<<GBA, T>>>(gtb, gtc, f8, f16, f32_);
    k_final<<<1, 1>>>(out);
}

// round 8
// speedup vs baseline: 2.0430x; 1.0184x over previous
#include <cuda_runtime.h>
#include <cuda_bf16.h>
#include <math.h>

#define NB 32
#define NG 60
#define NC 80
#define NA 8400
#define A0 6400
#define A1 8000
#define TK 10
#define NCH 33   // ceil(NA/256)
#define NCH64 132 // ceil(NA/64)

// ---------------- device scratch ----------------
__device__ float4 d_box[NB * NA];
__device__ float  d_obj[NB * NA];
__device__ unsigned char d_fg[NB * NA];
__device__ float4 d_geo[NA];
__device__ int    d_ccnt[NB * NCH];
__device__ int    d_fglist[NB * NA];
__device__ int    d_fgpos[NB * NA];
__device__ int    d_fgcnt[NB];
__device__ float4 d_boxC[NB * NA];
__device__ float4 d_geoC[NB * NA];
__device__ float  d_b0sC[NB * NA];
__device__ float  d_spsC[NB * NA];
__device__ float  d_dcoC[(size_t)NB * NC * NA];
__device__ int    d_cnt[NB * NA];
__device__ int    d_lastg[NB * NA];
__device__ int    d_matched[NB * NA];
__device__ float  d_prediou[NB * NA];
__device__ double d_acc[4];

__device__ __forceinline__ float iou_fn(float gx, float gy, float gw, float gh, float4 pb) {
    float tlx = fmaxf(gx - gw * 0.5f, pb.x - pb.z * 0.5f);
    float tly = fmaxf(gy - gh * 0.5f, pb.y - pb.w * 0.5f);
    float brx = fminf(gx + gw * 0.5f, pb.x + pb.z * 0.5f);
    float bry = fminf(gy + gh * 0.5f, pb.y + pb.w * 0.5f);
    bool en = (tlx < brx) && (tly < bry);
    float inter = en ? (brx - tlx) * (bry - tly) : 0.f;
    return inter / (gw * gh + pb.z * pb.w - inter + 1e-16f);
}

__device__ __forceinline__ float cost_fn(float gx, float gy, float gw, float gh,
                                         float iou, float cxa, float cya, float st,
                                         float b0s, float dco, bool valid, float c0) {
    const float R = 2.5f;
    bool in_box = (cxa > gx - 0.5f * gw) && (cxa < gx + 0.5f * gw) &&
                  (cya > gy - 0.5f * gh) && (cya < gy + 0.5f * gh);
    bool in_ctr = (cxa > gx - R * st) && (cxa < gx + R * st) &&
                  (cya > gy - R * st) && (cya < gy + R * st);
    bool in_both = in_box && in_ctr;
    float lt = (iou == 0.f) ? c0 : -logf(iou + 1e-8f);
    float cost = b0s + dco;
    cost += 3.0f * lt;
    cost += 100000.0f * (1.0f - (in_both ? 1.f : 0.f));
    cost += valid ? 0.f : 1000000000.0f;
    return cost;
}

// ---------------- kernels ----------------
// fused decode + fg + init; grid (NCH, NB)
__global__ void k_decode_fg(const float* __restrict__ f8,
                            const float* __restrict__ f16,
                            const float* __restrict__ f32_,
                            const float* __restrict__ gtb,
                            const int* __restrict__ ngts) {
    __shared__ float4 sgt[NG];
    int b = blockIdx.y;
    int n = ngts[b];
    if (threadIdx.x < NG) {
        const float* gbp = gtb + ((size_t)b * NG + threadIdx.x) * 4;
        sgt[threadIdx.x] = make_float4(gbp[0], gbp[1], gbp[2], gbp[3]);
    }
    __syncthreads();
    int a = blockIdx.x * blockDim.x + threadIdx.x;
    bool fg = false;
    if (a < NA) {
        int i = b * NA + a;
        d_cnt[i] = 0;
        if (i < 4) d_acc[i] = 0.0;
        const float* f; int hw, HW, W; float st;
        if (a < A0)      { f = f8;   hw = a;      HW = 6400; W = 80; st = 8.f;  }
        else if (a < A1) { f = f16;  hw = a - A0; HW = 1600; W = 40; st = 16.f; }
        else             { f = f32_; hw = a - A1; HW = 400;  W = 20; st = 32.f; }
        int xi = hw % W, yi = hw / W;
        float gx = (float)xi, gy = (float)yi;
        float cxa = (gx + 0.5f) * st, cya = (gy + 0.5f) * st;
        if (b == 0) d_geo[a] = make_float4(cxa, cya, st, 0.f);
        const float* base = f + (size_t)b * (5 + NC) * HW + hw;
        float tx = base[0 * HW], ty = base[(size_t)1 * HW];
        float tw = base[(size_t)2 * HW], th = base[(size_t)3 * HW];
        float to = base[(size_t)4 * HW];
        d_box[i] = make_float4((tx + gx) * st, (ty + gy) * st, expf(tw) * st, expf(th) * st);
        d_obj[i] = to;
        const float R = 2.5f;
        for (int g = 0; g < n; g++) {
            float4 gb = sgt[g];
            bool in_box = (cxa > gb.x - 0.5f * gb.z) && (cxa < gb.x + 0.5f * gb.z) &&
                          (cya > gb.y - 0.5f * gb.w) && (cya < gb.y + 0.5f * gb.w);
            bool in_ctr = (cxa > gb.x - R * st) && (cxa < gb.x + R * st) &&
                          (cya > gb.y - R * st) && (cya < gb.y + R * st);
            fg = fg || in_box || in_ctr;
        }
        d_fg[i] = fg ? 1 : 0;
    }
    int c = __syncthreads_count(fg ? 1 : 0);
    if (threadIdx.x == 0) d_ccnt[b * NCH + blockIdx.x] = c;
}

__global__ void k_compact() {
    __shared__ int swcnt[8];
    __shared__ int swoff[8];
    __shared__ int s_base;
    int b = blockIdx.y, ch = blockIdx.x, tid = threadIdx.x;
    int warp = tid >> 5, lane = tid & 31;
    if (warp == 0) {
        int v = 0;
        for (int c = lane; c < ch; c += 32) v += d_ccnt[b * NCH + c];
        for (int o = 16; o; o >>= 1) v += __shfl_xor_sync(0xffffffffu, v, o);
        if (lane == 0) s_base = v;
    }
    int a = ch * 256 + tid;
    bool flag = (a < NA) && d_fg[b * NA + a];
    unsigned bal = __ballot_sync(0xffffffffu, flag);
    int intra = __popc(bal & ((1u << lane) - 1u));
    if (lane == 0) swcnt[warp] = __popc(bal);
    __syncthreads();
    if (tid == 0) {
        int s = 0;
        for (int w = 0; w < 8; w++) { swoff[w] = s; s += swcnt[w]; }
        if (ch == NCH - 1) d_fgcnt[b] = s_base + s;
    }
    __syncthreads();
    if (flag) {
        int j = s_base + swoff[warp] + intra;
        d_fglist[b * NA + j] = a;
        d_fgpos[b * NA + a] = j;
        d_boxC[b * NA + j] = d_box[b * NA + a];
        d_geoC[b * NA + j] = d_geo[a];
    }
}

// class BCE precompute: 64 anchors x 4 class-groups per block; reduced math:
//   e = exp(-|x|); sps = max(x,0)+log1p(e); softplus(-x) = sps - x
//   bce1 = 0.5*(softplus(-x) + softplus(-to))   [== -log(sqrt(sc*so)), clip inactive]
//   bce0 = -log(1 - p)
__global__ void k_clsprep(const float* __restrict__ f8, const float* __restrict__ f16,
                          const float* __restrict__ f32_) {
    __shared__ float s_b0[256];
    __shared__ float s_sp[256];
    int b = blockIdx.y;
    int tid = threadIdx.x;
    int jl = tid & 63;
    int grp = tid >> 6;
    int j = blockIdx.x * 64 + jl;
    int cnt = d_fgcnt[b];
    float b0s = 0.f, sps = 0.f;
    if (j < cnt) {
        int a = d_fglist[b * NA + j];
        const float* f; int hw, HW;
        if (a < A0)      { f = f8;   hw = a;      HW = 6400; }
        else if (a < A1) { f = f16;  hw = a - A0; HW = 1600; }
        else             { f = f32_; hw = a - A1; HW = 400;  }
        const float* base = f + (size_t)b * (5 + NC) * HW + hw;
        float to = d_obj[b * NA + a];
        float eo = expf(-fabsf(to));
        float so = (to >= 0.f) ? 1.f / (1.f + eo) : eo / (1.f + eo);
        float spo = fmaxf(-to, 0.f) + log1pf(eo);   // softplus(-to)
        int c0i = grp * 20;
#pragma unroll 5
        for (int c = c0i; c < c0i + 20; c++) {
            float x = base[(size_t)(5 + c) * HW];
            float e = expf(-fabsf(x));
            float r = 1.f / (1.f + e);
            float sc = (x >= 0.f) ? r : e * r;
            float l1pe = log1pf(e);
            float sp = fmaxf(x, 0.f) + l1pe;        // softplus(x)
            float spn = sp - x;                      // softplus(-x)
            float p = sqrtf(sc * so);
            p = fminf(fmaxf(p, 1e-7f), 1.f - 1e-7f);
            float bce1 = 0.5f * (spn + spo);
            float bce0 = -logf(1.f - p);
            b0s += bce0;
            d_dcoC[((size_t)b * NC + c) * NA + j] = bce1 - bce0;
            sps += sp;
        }
    }
    s_b0[tid] = b0s;
    s_sp[tid] = sps;
    __syncthreads();
    if (grp == 0 && j < cnt) {
        float tb = (s_b0[jl] + s_b0[64 + jl]) + (s_b0[128 + jl] + s_b0[192 + jl]);
        float ts = (s_sp[jl] + s_sp[64 + jl]) + (s_sp[128 + jl] + s_sp[192 + jl]);
        d_b0sC[b * NA + j] = tb;
        d_spsC[b * NA + j] = ts;
    }
}

// fused cost+iou + top-k + inline scatter
__global__ void k_assign(const float* __restrict__ gtb, const int* __restrict__ gtc,
                         const int* __restrict__ ngts) {
    int g = blockIdx.x, b = blockIdx.y, tid = threadIdx.x;
    if (g >= ngts[b]) return;

    __shared__ float s_lv[256 * TK];
    __shared__ int   s_li[256 * TK];
    __shared__ int   s_head[256];

    const float c0 = -logf(1e-8f);

    const float* gb = gtb + ((size_t)b * NG + g) * 4;
    float gx = gb[0], gy = gb[1], gw = gb[2], gh = gb[3];
    int gc = gtc[b * NG + g];
    int cnt = d_fgcnt[b];

    const float4* boxp = d_boxC + b * NA;
    const float4* geop = d_geoC + b * NA;
    const float* b0p = d_b0sC + b * NA;
    const float* dcop = d_dcoC + ((size_t)b * NC + gc) * NA;

    float iv[TK]; int ii[TK];
    float cv[TK]; int ci[TK];
#pragma unroll
    for (int k = 0; k < TK; k++) { iv[k] = -1.f; ii[k] = 0x7fffffff; cv[k] = 3.4e38f; ci[k] = 0x7fffffff; }

    for (int j = tid; j < cnt; j += 256) {
        float4 pb = boxp[j];
        float iou = iou_fn(gx, gy, gw, gh, pb);
        if (iou > iv[TK - 1] || (iou == iv[TK - 1] && j < ii[TK - 1])) {
            iv[TK - 1] = iou; ii[TK - 1] = j;
#pragma unroll
            for (int k = TK - 1; k > 0; k--) {
                if (iv[k] > iv[k - 1] || (iv[k] == iv[k - 1] && ii[k] < ii[k - 1])) {
                    float tv = iv[k]; iv[k] = iv[k - 1]; iv[k - 1] = tv;
                    int ti = ii[k]; ii[k] = ii[k - 1]; ii[k - 1] = ti;
                }
            }
        }
        float4 ge = geop[j];
        float cost = cost_fn(gx, gy, gw, gh, iou, ge.x, ge.y, ge.z, b0p[j], dcop[j], true, c0);
        if (cost < cv[TK - 1] || (cost == cv[TK - 1] && j < ci[TK - 1])) {
            cv[TK - 1] = cost; ci[TK - 1] = j;
#pragma unroll
            for (int k = TK - 1; k > 0; k--) {
                if (cv[k] < cv[k - 1] || (cv[k] == cv[k - 1] && ci[k] < ci[k - 1])) {
                    float tv = cv[k]; cv[k] = cv[k - 1]; cv[k - 1] = tv;
                    int ti = ci[k]; ci[k] = ci[k - 1]; ci[k - 1] = ti;
                }
            }
        }
    }

    int dk_local = 1;

#pragma unroll
    for (int k = 0; k < TK; k++) { s_lv[tid * TK + k] = iv[k]; s_li[tid * TK + k] = ii[k]; }
    __syncthreads();
    if (tid < 32) {
        for (int l = tid; l < 256; l += 32) s_head[l] = 0;
        __syncwarp();
        float ksum = 0.f;
        for (int r = 0; r < TK; r++) {
            float bv = -2.f; int bi = 0x7fffffff; int bl = -1;
            for (int k = 0; k < 8; k++) {
                int l = tid + 32 * k;
                int hd = s_head[l];
                float v = s_lv[l * TK + hd]; int idx = s_li[l * TK + hd];
                if (v > bv || (v == bv && idx < bi)) { bv = v; bi = idx; bl = l; }
            }
            for (int o = 16; o; o >>= 1) {
                float ov = __shfl_xor_sync(0xffffffffu, bv, o);
                int oi = __shfl_xor_sync(0xffffffffu, bi, o);
                int ol = __shfl_xor_sync(0xffffffffu, bl, o);
                if (ov > bv || (ov == bv && oi < bi)) { bv = ov; bi = oi; bl = ol; }
            }
            ksum += fmaxf(bv, 0.f);
            if (tid == 0) s_head[bl]++;
            __syncwarp();
        }
        if (tid == 0) {
            dk_local = (int)ksum;
            if (dk_local < 1) dk_local = 1;
        }
    }
    __syncthreads();

#pragma unroll
    for (int k = 0; k < TK; k++) { s_lv[tid * TK + k] = cv[k]; s_li[tid * TK + k] = ci[k]; }
    __syncthreads();
    if (tid < 32) {
        for (int l = tid; l < 256; l += 32) s_head[l] = 0;
        __syncwarp();
        int pa[TK];
        for (int r = 0; r < TK; r++) {
            float bv = 3.5e38f; int bi = 0x7fffffff; int bl = -1;
            for (int k = 0; k < 8; k++) {
                int l = tid + 32 * k;
                int hd = s_head[l];
                float v = s_lv[l * TK + hd]; int idx = s_li[l * TK + hd];
                if (v < bv || (v == bv && idx < bi)) { bv = v; bi = idx; bl = l; }
            }
            for (int o = 16; o; o >>= 1) {
                float ov = __shfl_xor_sync(0xffffffffu, bv, o);
                int oi = __shfl_xor_sync(0xffffffffu, bi, o);
                int ol = __shfl_xor_sync(0xffffffffu, bl, o);
                if (ov < bv || (ov == bv && oi < bi)) { bv = ov; bi = oi; bl = ol; }
            }
            if (tid == 0) {
                pa[r] = bi;
                s_head[bl]++;
            }
            __syncwarp();
        }
        if (tid == 0) {
            for (int r = 0; r < dk_local; r++) {
                int a = d_fglist[b * NA + pa[r]];
                atomicAdd(&d_cnt[b * NA + a], 1);
                d_lastg[b * NA + a] = g;
            }
        }
    }
}

__global__ void k_resolve(const float* __restrict__ gtb, const int* __restrict__ gtc,
                          const int* __restrict__ ngts) {
    int i = blockIdx.x * blockDim.x + threadIdx.x;
    if (i >= NB * NA) return;
    int c = d_cnt[i];
    if (c == 0) { d_matched[i] = -1; d_prediou[i] = 0.f; return; }
    int b = i / NA, a = i % NA;
    float4 pb = d_box[i];
    int mg;
    if (c == 1) {
        mg = d_lastg[i];
    } else {
        const float c0 = -logf(1e-8f);
        int n = ngts[b];
        int j = d_fgpos[i];
        float4 ge = d_geo[a];
        float b0s = d_b0sC[b * NA + j];
        float best = 3.5e38f; int bi = 0;
        for (int g = 0; g < NG; g++) {
            const float* gb = gtb + ((size_t)b * NG + g) * 4;
            float gx = gb[0], gy = gb[1], gw = gb[2], gh = gb[3];
            int gc = gtc[b * NG + g];
            float iou = iou_fn(gx, gy, gw, gh, pb);
            float dco = d_dcoC[((size_t)b * NC + gc) * NA + j];
            float cv = cost_fn(gx, gy, gw, gh, iou, ge.x, ge.y, ge.z, b0s, dco, g < n, c0);
            if (cv < best) { best = cv; bi = g; }
        }
        mg = bi;
    }
    d_matched[i] = mg;
    const float* gb = gtb + ((size_t)b * NG + mg) * 4;
    d_prediou[i] = iou_fn(gb[0], gb[1], gb[2], gb[3], pb);
}

__global__ void k_loss(const float* __restrict__ gtb, const int* __restrict__ gtc,
                       const float* __restrict__ f8, const float* __restrict__ f16,
                       const float* __restrict__ f32_) {
    __shared__ float s1[256], s2[256], s3[256];
    __shared__ int   s4[256];
    int tid = threadIdx.x;
    int i = blockIdx.x * blockDim.x + tid;
    float liou = 0.f, lobj = 0.f, lcls = 0.f; int nfg = 0;
    if (i < NB * NA) {
        int b = i / NA, a = i % NA;
        int mg = d_matched[i];
        bool fg = mg >= 0;
        float tgt = fg ? 0.9f : 0.f;
        float x = d_obj[i];
        lobj = fmaxf(x, 0.f) - x * tgt + log1pf(expf(-fabsf(x)));
        if (fg) {
            nfg = 1;
            const float* gb = gtb + ((size_t)b * NG + mg) * 4;
            float gx = gb[0], gy = gb[1], gw = gb[2], gh = gb[3];
            float4 pb = d_box[i];
            float tlx = fmaxf(pb.x - pb.z * 0.5f, gx - gw * 0.5f);
            float tly = fmaxf(pb.y - pb.w * 0.5f, gy - gh * 0.5f);
            float brx = fminf(pb.x + pb.z * 0.5f, gx + gw * 0.5f);
            float bry = fminf(pb.y + pb.w * 0.5f, gy + gh * 0.5f);
            bool en = (tlx < brx) && (tly < bry);
            float inter = en ? (brx - tlx) * (bry - tly) : 0.f;
            float uni = pb.z * pb.w + gw * gh - inter;
            float iou = inter / (uni + 1e-16f);
            liou = 1.f - iou * iou;
            int gc = gtc[b * NG + mg];
            const float* f; int hw, HW;
            if (a < A0)      { f = f8;   hw = a;      HW = 6400; }
            else if (a < A1) { f = f16;  hw = a - A0; HW = 1600; }
            else             { f = f32_; hw = a - A1; HW = 400;  }
            float cl = f[((size_t)b * (5 + NC) + 5 + gc) * HW + hw];
            lcls = d_spsC[b * NA + d_fgpos[i]] - cl * d_prediou[i];
        }
    }
    s1[tid] = liou; s2[tid] = lobj; s3[tid] = lcls; s4[tid] = nfg;
    __syncthreads();
    for (int s = 128; s > 0; s >>= 1) {
        if (tid < s) {
            s1[tid] += s1[tid + s]; s2[tid] += s2[tid + s];
            s3[tid] += s3[tid + s]; s4[tid] += s4[tid + s];
        }
        __syncthreads();
    }
    if (tid == 0) {
        atomicAdd(&d_acc[0], (double)s1[0]);
        atomicAdd(&d_acc[1], (double)s2[0]);
        atomicAdd(&d_acc[2], (double)s3[0]);
        atomicAdd(&d_acc[3], (double)s4[0]);
    }
}

__global__ void k_final(float* out) {
    double nfg = d_acc[3];
    if (nfg < 1.0) nfg = 1.0;
    out[0] = (float)((5.0 * d_acc[0] + d_acc[1] + d_acc[2]) / nfg);
}

// ---------------- launch ----------------
extern "C" void kernel_launch(void* const* d_in, const int* in_sizes, int n_in,
                              void* d_out, int out_size) {
    const float* f8   = (const float*)d_in[0];
    const float* f16  = (const float*)d_in[1];
    const float* f32_ = (const float*)d_in[2];
    const float* gtb  = (const float*)d_in[3];
    const int*   gtc  = (const int*)d_in[4];
    const int*   ngts = (const int*)d_in[5];
    float* out = (float*)d_out;

    const int NBA = NB * NA;
    const int T = 256;
    const int GBA = (NBA + T - 1) / T;

    k_decode_fg<<<dim3(NCH, NB), T>>>(f8, f16, f32_, gtb, ngts);
    k_compact<<<dim3(NCH, NB), T>>>();
    k_clsprep<<<dim3(NCH64, NB), T>>>(f8, f16, f32_);
    k_assign<<<dim3(NG, NB), T>>>(gtb, gtc, ngts);
    k_resolve<<<GBA, T>>>(gtb, gtc, ngts);
    k_loss<<<GBA, T>>>(gtb, gtc, f8, f16, f32_);
    k_final<<<1, 1>>>(out);
}